// round 1
// baseline (speedup 1.0000x reference)
#include <cuda_runtime.h>
#include <cuda_bf16.h>
#include <cstddef>

#define BB 4
#define T0C 256
#define T1C 768
#define TC 1024
#define DC 2048
#define NQ 8
#define HC 256
#define FC 16384
#define NHD 2048
#define NEGC (-2.3819763e+38f)

// ---------------- static scratch (no allocation allowed) ----------------
__device__ float g_pre  [(size_t)BB*TC*DC];
__device__ float g_qlin [(size_t)BB*TC*NHD];
__device__ float g_q    [(size_t)BB*TC*NHD];
__device__ float g_klin [(size_t)BB*TC*HC];
__device__ float g_kT   [(size_t)BB*HC*TC];
__device__ float g_v    [(size_t)BB*TC*HC];
__device__ float g_enc  [(size_t)BB*TC*NHD];
__device__ float g_resid[(size_t)BB*TC*DC];
__device__ float g_hid  [(size_t)BB*TC*DC];
__device__ float g_gu   [(size_t)BB*TC*FC];

__device__ __forceinline__ float warp_sum(float v) {
    #pragma unroll
    for (int o = 16; o; o >>= 1) v += __shfl_down_sync(0xffffffffu, v, o);
    return v;
}

__device__ __forceinline__ float gelu_tanh(float x) {
    float x3 = x * x * x;
    return 0.5f * x * (1.f + tanhf(0.7978845608028654f * (x + 0.044715f * x3)));
}

// ---------------- RMSNorm on segmented inputs (x0|x1) ----------------
__global__ void rms_seg_kernel(const float* __restrict__ x0, const float* __restrict__ x1,
                               const float* __restrict__ s0, const float* __restrict__ s1,
                               float* __restrict__ out) {
    int row = blockIdx.x;
    int b = row >> 10, t = row & 1023;
    const float* x; const float* s;
    if (t < T0C) { x = x0 + ((size_t)b*T0C + t)*DC; s = s0; }
    else         { x = x1 + ((size_t)b*T1C + (t - T0C))*DC; s = s1; }
    float ss = 0.f;
    for (int d = threadIdx.x; d < DC; d += 256) { float v = x[d]; ss += v*v; }
    __shared__ float red[8];
    ss = warp_sum(ss);
    if ((threadIdx.x & 31) == 0) red[threadIdx.x >> 5] = ss;
    __syncthreads();
    if (threadIdx.x < 8) {
        float v = red[threadIdx.x];
        #pragma unroll
        for (int o = 4; o; o >>= 1) v += __shfl_down_sync(0xffu, v, o);
        if (threadIdx.x == 0) red[0] = v;
    }
    __syncthreads();
    float inv = rsqrtf(red[0] * (1.f / DC) + 1e-6f);
    float* o = out + (size_t)row * DC;
    for (int d = threadIdx.x; d < DC; d += 256) o[d] = x[d] * inv * (1.f + s[d]);
}

// ---------------- RMSNorm on contiguous input ----------------
__global__ void rms_cont_kernel(const float* __restrict__ xin,
                                const float* __restrict__ s0, const float* __restrict__ s1,
                                float* __restrict__ out) {
    int row = blockIdx.x;
    int t = row & 1023;
    const float* x = xin + (size_t)row * DC;
    const float* s = (t < T0C) ? s0 : s1;
    float ss = 0.f;
    for (int d = threadIdx.x; d < DC; d += 256) { float v = x[d]; ss += v*v; }
    __shared__ float red[8];
    ss = warp_sum(ss);
    if ((threadIdx.x & 31) == 0) red[threadIdx.x >> 5] = ss;
    __syncthreads();
    if (threadIdx.x < 8) {
        float v = red[threadIdx.x];
        #pragma unroll
        for (int o = 4; o; o >>= 1) v += __shfl_down_sync(0xffu, v, o);
        if (threadIdx.x == 0) red[0] = v;
    }
    __syncthreads();
    float inv = rsqrtf(red[0] * (1.f / DC) + 1e-6f);
    float* o = out + (size_t)row * DC;
    for (int d = threadIdx.x; d < DC; d += 256) o[d] = x[d] * inv * (1.f + s[d]);
}

// ---------------- generic segmented-weight GEMM: C = A @ W.T (+epilogue) ----------------
// MODE 0: C[r*Nout+c] = acc
// MODE 1: C[r*D+c] = acc + X(seg)     (o-proj + residual)
// MODE 2: d_out[segmented r,c] = acc + Radd[r*D+c]   (down-proj + residual, scatter)
template <int MODE>
__global__ void gemm_kernel(const float* __restrict__ A,
                            const float* __restrict__ W0, const float* __restrict__ W1,
                            float* __restrict__ C, int Nout, int Kdim,
                            const float* __restrict__ X0, const float* __restrict__ X1,
                            const float* __restrict__ Radd) {
    __shared__ float As[16][68];
    __shared__ float Ws[16][68];
    int rm0 = blockIdx.y * 64, rn0 = blockIdx.x * 64;
    const float* W = ((rm0 & 1023) < T0C) ? W0 : W1;
    int tid = threadIdx.x;
    int lm = tid >> 2;            // 0..63
    int lk = (tid & 3) * 4;       // 0,4,8,12
    int ty = tid >> 4, tx = tid & 15;
    float acc[4][4] = {};
    const float* Ap = A + (size_t)(rm0 + lm) * Kdim + lk;
    const float* Wp = W + (size_t)(rn0 + lm) * Kdim + lk;
    for (int kb = 0; kb < Kdim; kb += 16) {
        float4 a4 = *(const float4*)(Ap + kb);
        float4 w4 = *(const float4*)(Wp + kb);
        __syncthreads();
        As[lk+0][lm] = a4.x; As[lk+1][lm] = a4.y; As[lk+2][lm] = a4.z; As[lk+3][lm] = a4.w;
        Ws[lk+0][lm] = w4.x; Ws[lk+1][lm] = w4.y; Ws[lk+2][lm] = w4.z; Ws[lk+3][lm] = w4.w;
        __syncthreads();
        #pragma unroll
        for (int kk = 0; kk < 16; kk++) {
            float4 av = *(const float4*)&As[kk][ty*4];
            float4 wv = *(const float4*)&Ws[kk][tx*4];
            float aa[4] = {av.x, av.y, av.z, av.w};
            float ww[4] = {wv.x, wv.y, wv.z, wv.w};
            #pragma unroll
            for (int i = 0; i < 4; i++)
                #pragma unroll
                for (int j = 0; j < 4; j++)
                    acc[i][j] += aa[i] * ww[j];
        }
    }
    #pragma unroll
    for (int i = 0; i < 4; i++) {
        int r = rm0 + ty*4 + i;
        #pragma unroll
        for (int j = 0; j < 4; j++) {
            int c = rn0 + tx*4 + j;
            if (MODE == 0) {
                C[(size_t)r * Nout + c] = acc[i][j];
            } else if (MODE == 1) {
                int b = r >> 10, t = r & 1023;
                float xv = (t < T0C) ? X0[((size_t)b*T0C + t)*DC + c]
                                     : X1[((size_t)b*T1C + (t - T0C))*DC + c];
                C[(size_t)r * DC + c] = acc[i][j] + xv;
            } else {
                int b = r >> 10, t = r & 1023;
                float rv = Radd[(size_t)r * DC + c];
                size_t dst = (t < T0C) ? ((size_t)b*T0C + t)*DC + c
                                       : (size_t)BB*T0C*DC + ((size_t)b*T1C + (t - T0C))*DC + c;
                C[dst] = acc[i][j] + rv;
            }
        }
    }
}

// ---------------- fused gate/up GEMM: out = gelu(A@gw.T) * (A@uw.T) ----------------
__global__ void ffn1_kernel(const float* __restrict__ A,
                            const float* __restrict__ gw0, const float* __restrict__ gw1,
                            const float* __restrict__ uw0, const float* __restrict__ uw1,
                            float* __restrict__ out) {
    __shared__ float As[16][68];
    __shared__ float Gs[16][68];
    __shared__ float Us[16][68];
    int rm0 = blockIdx.y * 64, rn0 = blockIdx.x * 64;
    int seg1 = ((rm0 & 1023) >= T0C);
    const float* GW = seg1 ? gw1 : gw0;
    const float* UW = seg1 ? uw1 : uw0;
    int tid = threadIdx.x;
    int lm = tid >> 2;
    int lk = (tid & 3) * 4;
    int ty = tid >> 4, tx = tid & 15;
    float accg[4][4] = {}, accu[4][4] = {};
    const float* Ap = A  + (size_t)(rm0 + lm) * DC + lk;
    const float* Gp = GW + (size_t)(rn0 + lm) * DC + lk;
    const float* Up = UW + (size_t)(rn0 + lm) * DC + lk;
    for (int kb = 0; kb < DC; kb += 16) {
        float4 a4 = *(const float4*)(Ap + kb);
        float4 g4 = *(const float4*)(Gp + kb);
        float4 u4 = *(const float4*)(Up + kb);
        __syncthreads();
        As[lk+0][lm] = a4.x; As[lk+1][lm] = a4.y; As[lk+2][lm] = a4.z; As[lk+3][lm] = a4.w;
        Gs[lk+0][lm] = g4.x; Gs[lk+1][lm] = g4.y; Gs[lk+2][lm] = g4.z; Gs[lk+3][lm] = g4.w;
        Us[lk+0][lm] = u4.x; Us[lk+1][lm] = u4.y; Us[lk+2][lm] = u4.z; Us[lk+3][lm] = u4.w;
        __syncthreads();
        #pragma unroll
        for (int kk = 0; kk < 16; kk++) {
            float4 av = *(const float4*)&As[kk][ty*4];
            float4 gv = *(const float4*)&Gs[kk][tx*4];
            float4 uv = *(const float4*)&Us[kk][tx*4];
            float aa[4] = {av.x, av.y, av.z, av.w};
            float gg[4] = {gv.x, gv.y, gv.z, gv.w};
            float uu[4] = {uv.x, uv.y, uv.z, uv.w};
            #pragma unroll
            for (int i = 0; i < 4; i++)
                #pragma unroll
                for (int j = 0; j < 4; j++) {
                    accg[i][j] += aa[i] * gg[j];
                    accu[i][j] += aa[i] * uu[j];
                }
        }
    }
    #pragma unroll
    for (int i = 0; i < 4; i++) {
        int r = rm0 + ty*4 + i;
        #pragma unroll
        for (int j = 0; j < 4; j++) {
            int c = rn0 + tx*4 + j;
            out[(size_t)r * FC + c] = gelu_tanh(accg[i][j]) * accu[i][j];
        }
    }
}

// ---------------- RoPE on q (scaled by H^-0.5) ----------------
__global__ void rope_q_kernel(const float* __restrict__ qlin, float* __restrict__ qout) {
    int head = blockIdx.x;             // b*T*NQ + n layout: head = bt*NQ + n
    int bt = head >> 3;
    int t = bt & 1023;
    int i = threadIdx.x;               // 0..127
    float fe = (float)i * (1.f / 128.f);
    float ts = powf(10000.f, fe);
    float rad = (float)t / ts;
    float s, c;
    sincosf(rad, &s, &c);
    size_t base = (size_t)head * HC;
    float x1 = qlin[base + i], x2 = qlin[base + 128 + i];
    const float sc = 0.0625f;          // 256^-0.5
    qout[base + i]       = (x1 * c - x2 * s) * sc;
    qout[base + 128 + i] = (x2 * c + x1 * s) * sc;
}

// ---------------- RoPE on k, written transposed [b][d][t] ----------------
__global__ void rope_k_kernel(const float* __restrict__ klin, float* __restrict__ kT) {
    int bt = blockIdx.x;
    int b = bt >> 10, t = bt & 1023;
    int i = threadIdx.x;
    float fe = (float)i * (1.f / 128.f);
    float ts = powf(10000.f, fe);
    float rad = (float)t / ts;
    float s, c;
    sincosf(rad, &s, &c);
    size_t base = (size_t)bt * HC;
    float x1 = klin[base + i], x2 = klin[base + 128 + i];
    kT[((size_t)b * HC + i) * TC + t]       = x1 * c - x2 * s;
    kT[((size_t)b * HC + 128 + i) * TC + t] = x2 * c + x1 * s;
}

// ---------------- attention: per (b, head, 8-query) block, two-pass softmax ----------------
__global__ void attn_kernel(const float* __restrict__ q, const float* __restrict__ kT,
                            const float* __restrict__ v, float* __restrict__ enc) {
    int qt0 = blockIdx.x * 8;
    int n = blockIdx.y, b = blockIdx.z;
    __shared__ float qs[8][HC];
    __shared__ float sc[8][TC];
    int tid = threadIdx.x;
    for (int idx = tid; idx < 8 * HC; idx += 256) {
        int qi = idx >> 8, h = idx & 255;
        qs[qi][h] = q[(((size_t)b * TC + qt0 + qi) * NQ + n) * HC + h];
    }
    __syncthreads();
    int w = tid >> 5, lane = tid & 31;
    int t = qt0 + w;
    const float* kTb = kT + (size_t)b * HC * TC;
    // pass 1: scores
    for (int j = lane; j < TC; j += 32) {
        float s = 0.f;
        #pragma unroll 8
        for (int d = 0; d < HC; d++)
            s += qs[w][d] * kTb[(size_t)d * TC + j];
        bool valid = (j < T0C) || (t >= T0C && j <= t);
        sc[w][j] = valid ? s : NEGC;
    }
    // softmax (warp-private row)
    float m = -3.4e38f;
    for (int j = lane; j < TC; j += 32) m = fmaxf(m, sc[w][j]);
    #pragma unroll
    for (int o = 16; o; o >>= 1) m = fmaxf(m, __shfl_xor_sync(0xffffffffu, m, o));
    float l = 0.f;
    for (int j = lane; j < TC; j += 32) {
        float p = expf(sc[w][j] - m);
        sc[w][j] = p;
        l += p;
    }
    #pragma unroll
    for (int o = 16; o; o >>= 1) l += __shfl_xor_sync(0xffffffffu, l, o);
    float linv = 1.f / l;
    __syncwarp();
    // pass 2: probs @ v
    float acc[8] = {};
    const float* vb = v + (size_t)b * TC * HC;
    for (int j = 0; j < TC; j++) {
        float p = sc[w][j];
        #pragma unroll
        for (int hh = 0; hh < 8; hh++)
            acc[hh] += p * vb[(size_t)j * HC + lane + 32 * hh];
    }
    #pragma unroll
    for (int hh = 0; hh < 8; hh++)
        enc[(((size_t)b * TC + t) * NQ + n) * HC + lane + 32 * hh] = acc[hh] * linv;
}

// ---------------- launch ----------------
extern "C" void kernel_launch(void* const* d_in, const int* in_sizes, int n_in,
                              void* d_out, int out_size) {
    const float* x0  = (const float*)d_in[0];
    const float* x1  = (const float*)d_in[1];
    // d_in[2] positions, d_in[3] mask: analytic, unused
    const float* qw0 = (const float*)d_in[4];
    const float* kw0 = (const float*)d_in[5];
    const float* vw0 = (const float*)d_in[6];
    const float* ow0 = (const float*)d_in[7];
    const float* gw0 = (const float*)d_in[8];
    const float* uw0 = (const float*)d_in[9];
    const float* dw0 = (const float*)d_in[10];
    const float* pa0 = (const float*)d_in[11];
    const float* pf0 = (const float*)d_in[12];
    const float* qw1 = (const float*)d_in[13];
    const float* kw1 = (const float*)d_in[14];
    const float* vw1 = (const float*)d_in[15];
    const float* ow1 = (const float*)d_in[16];
    const float* gw1 = (const float*)d_in[17];
    const float* uw1 = (const float*)d_in[18];
    const float* dw1 = (const float*)d_in[19];
    const float* pa1 = (const float*)d_in[20];
    const float* pf1 = (const float*)d_in[21];

    float *pre, *qlin, *qb, *klin, *kT, *vb, *enc, *resid, *hid, *gu;
    cudaGetSymbolAddress((void**)&pre,   g_pre);
    cudaGetSymbolAddress((void**)&qlin,  g_qlin);
    cudaGetSymbolAddress((void**)&qb,    g_q);
    cudaGetSymbolAddress((void**)&klin,  g_klin);
    cudaGetSymbolAddress((void**)&kT,    g_kT);
    cudaGetSymbolAddress((void**)&vb,    g_v);
    cudaGetSymbolAddress((void**)&enc,   g_enc);
    cudaGetSymbolAddress((void**)&resid, g_resid);
    cudaGetSymbolAddress((void**)&hid,   g_hid);
    cudaGetSymbolAddress((void**)&gu,    g_gu);

    // 1. pre = RMSNorm(x)
    rms_seg_kernel<<<BB * TC, 256>>>(x0, x1, pa0, pa1, pre);
    // 2. QKV projections
    gemm_kernel<0><<<dim3(NHD/64, BB*TC/64), 256>>>(pre, qw0, qw1, qlin, NHD, DC, nullptr, nullptr, nullptr);
    gemm_kernel<0><<<dim3(HC/64,  BB*TC/64), 256>>>(pre, kw0, kw1, klin, HC,  DC, nullptr, nullptr, nullptr);
    gemm_kernel<0><<<dim3(HC/64,  BB*TC/64), 256>>>(pre, vw0, vw1, vb,   HC,  DC, nullptr, nullptr, nullptr);
    // 3. RoPE
    rope_q_kernel<<<BB * TC * NQ, 128>>>(qlin, qb);
    rope_k_kernel<<<BB * TC, 128>>>(klin, kT);
    // 4. attention
    attn_kernel<<<dim3(TC/8, NQ, BB), 256>>>(qb, kT, vb, enc);
    // 5. O-proj + residual
    gemm_kernel<1><<<dim3(DC/64, BB*TC/64), 256>>>(enc, ow0, ow1, resid, DC, NHD, x0, x1, nullptr);
    // 6. hidden = RMSNorm(resid)
    rms_cont_kernel<<<BB * TC, 256>>>(resid, pf0, pf1, hid);
    // 7. fused gate/up
    ffn1_kernel<<<dim3(FC/64, BB*TC/64), 256>>>(hid, gw0, gw1, uw0, uw1, gu);
    // 8. down-proj + residual, scatter to segmented output
    gemm_kernel<2><<<dim3(DC/64, BB*TC/64), 256>>>(gu, dw0, dw1, (float*)d_out, DC, FC, nullptr, nullptr, resid);
}

// round 3
// speedup vs baseline: 2.4082x; 2.4082x over previous
#include <cuda_runtime.h>
#include <cuda_bf16.h>
#include <cstdint>
#include <cstddef>

#define BB 4
#define T0C 256
#define T1C 768
#define TC 1024
#define DC 2048
#define NQ 8
#define HC 256
#define FC 16384
#define NHD 2048
#define NEGC (-2.3819763e+38f)

// ---------------- static scratch ----------------
__device__ float g_pre  [(size_t)BB*TC*DC];
__device__ float g_qlin [(size_t)BB*TC*NHD];
__device__ float g_q    [(size_t)BB*TC*NHD];
__device__ float g_klin [(size_t)BB*TC*HC];
__device__ float g_kT   [(size_t)BB*HC*TC];
__device__ float g_v    [(size_t)BB*TC*HC];
__device__ float g_enc  [(size_t)BB*TC*NHD];
__device__ float g_resid[(size_t)BB*TC*DC];
__device__ float g_hid  [(size_t)BB*TC*DC];
__device__ float g_gu   [(size_t)BB*TC*FC];

__device__ __forceinline__ uint32_t f2tf32(float f) {
    uint32_t r;
    asm("cvt.rna.tf32.f32 %0, %1;" : "=r"(r) : "f"(f));
    return r;
}

__device__ __forceinline__ void mma8(float* d, const uint32_t* a, const uint32_t* b) {
    asm volatile(
        "mma.sync.aligned.m16n8k8.row.col.f32.tf32.tf32.f32 "
        "{%0,%1,%2,%3}, {%4,%5,%6,%7}, {%8,%9}, {%0,%1,%2,%3};"
        : "+f"(d[0]), "+f"(d[1]), "+f"(d[2]), "+f"(d[3])
        : "r"(a[0]), "r"(a[1]), "r"(a[2]), "r"(a[3]), "r"(b[0]), "r"(b[1]));
}

__device__ __forceinline__ float gelu_tanh(float x) {
    float x3 = x * x * x;
    return 0.5f * x * (1.f + tanhf(0.7978845608028654f * (x + 0.044715f * x3)));
}

// ================= mma.sync tf32 GEMM =================
// C[4096, Nout] = A[4096, Kdim] @ W.T, weights chosen per 128-row segment.
// MODE 0: store acc
// MODE 1: store acc + X(segmented x0/x1)          (o-proj + residual)
// MODE 2: store acc + Radd, scattered to d_out    (down-proj + residual)
// MODE 4: store gelu(acc)                         (gate pass)
// MODE 5: store acc * C_existing                  (up pass, RMW on C)
#define SROW 36
#define SSTG (128 * SROW * 2)

template <int MODE>
__global__ void __launch_bounds__(256, 1)
mma_gemm(const float* __restrict__ A,
         const float* __restrict__ W0, const float* __restrict__ W1,
         float* __restrict__ C, int Nout, int Kdim,
         const float* __restrict__ X0, const float* __restrict__ X1,
         const float* __restrict__ Radd) {
    extern __shared__ float smf[];
    int tid = threadIdx.x, wid = tid >> 5, lane = tid & 31;
    int warp_m = wid & 3, warp_n = wid >> 2;
    int rm0 = blockIdx.x * 128;
    int rn0 = blockIdx.y * 128;
    const float* W = ((rm0 & 1023) < T0C) ? W0 : W1;

    float acc[2][8][4];
    #pragma unroll
    for (int t = 0; t < 2; t++)
        #pragma unroll
        for (int j = 0; j < 8; j++)
            #pragma unroll
            for (int e = 0; e < 4; e++) acc[t][j][e] = 0.f;

    float4 ra[4], rw[4];

    auto ldchunk = [&](int kb) {
        #pragma unroll
        for (int it = 0; it < 4; it++) {
            int idx = it * 256 + tid;
            int row = idx >> 3, c4 = (idx & 7) << 2;
            ra[it] = *(const float4*)(A + (size_t)(rm0 + row) * Kdim + kb + c4);
            rw[it] = *(const float4*)(W + (size_t)(rn0 + row) * Kdim + kb + c4);
        }
    };
    auto stchunk = [&](int buf) {
        float* As = smf + buf * SSTG;
        float* Ws = As + 128 * SROW;
        #pragma unroll
        for (int it = 0; it < 4; it++) {
            int idx = it * 256 + tid;
            int row = idx >> 3, c4 = (idx & 7) << 2;
            uint4 ta, tw;
            ta.x = f2tf32(ra[it].x); ta.y = f2tf32(ra[it].y);
            ta.z = f2tf32(ra[it].z); ta.w = f2tf32(ra[it].w);
            tw.x = f2tf32(rw[it].x); tw.y = f2tf32(rw[it].y);
            tw.z = f2tf32(rw[it].z); tw.w = f2tf32(rw[it].w);
            *(uint4*)&As[row * SROW + c4] = ta;
            *(uint4*)&Ws[row * SROW + c4] = tw;
        }
    };
    auto compute = [&](int buf) {
        const float* As = smf + buf * SSTG;
        const float* Ws = As + 128 * SROW;
        int ar = warp_m * 32 + (lane >> 2);
        int br = warp_n * 64 + (lane >> 2);
        #pragma unroll
        for (int ks = 0; ks < 4; ks++) {
            int ac = ks * 8 + (lane & 3);
            uint32_t af[2][4], bf[8][2];
            #pragma unroll
            for (int t = 0; t < 2; t++) {
                const float* p = &As[(ar + t * 16) * SROW + ac];
                af[t][0] = __float_as_uint(p[0]);
                af[t][1] = __float_as_uint(p[8 * SROW]);
                af[t][2] = __float_as_uint(p[4]);
                af[t][3] = __float_as_uint(p[8 * SROW + 4]);
            }
            #pragma unroll
            for (int j = 0; j < 8; j++) {
                const float* p = &Ws[(br + j * 8) * SROW + ac];
                bf[j][0] = __float_as_uint(p[0]);
                bf[j][1] = __float_as_uint(p[4]);
            }
            #pragma unroll
            for (int t = 0; t < 2; t++)
                #pragma unroll
                for (int j = 0; j < 8; j++)
                    mma8(acc[t][j], af[t], bf[j]);
        }
    };

    const int nch = Kdim >> 5;
    ldchunk(0);
    stchunk(0);
    __syncthreads();
    for (int c = 0; c < nch; c++) {
        if (c + 1 < nch) ldchunk((c + 1) << 5);
        compute(c & 1);
        if (c + 1 < nch) { stchunk((c + 1) & 1); __syncthreads(); }
    }

    // ---------------- epilogue ----------------
    #pragma unroll
    for (int t = 0; t < 2; t++) {
        #pragma unroll
        for (int j = 0; j < 8; j++) {
            int c = rn0 + warp_n * 64 + j * 8 + (lane & 3) * 2;
            #pragma unroll
            for (int h = 0; h < 2; h++) {
                int r = rm0 + warp_m * 32 + t * 16 + (lane >> 2) + h * 8;
                float v0 = acc[t][j][h * 2 + 0];
                float v1 = acc[t][j][h * 2 + 1];
                if (MODE == 0) {
                    float2 v = {v0, v1};
                    *(float2*)&C[(size_t)r * Nout + c] = v;
                } else if (MODE == 1) {
                    int b = r >> 10, tt = r & 1023;
                    const float* xp = (tt < T0C)
                        ? X0 + ((size_t)b * T0C + tt) * DC + c
                        : X1 + ((size_t)b * T1C + (tt - T0C)) * DC + c;
                    float2 xv = *(const float2*)xp;
                    float2 v = {v0 + xv.x, v1 + xv.y};
                    *(float2*)&C[(size_t)r * DC + c] = v;
                } else if (MODE == 2) {
                    float2 rv = *(const float2*)&Radd[(size_t)r * DC + c];
                    int b = r >> 10, tt = r & 1023;
                    size_t dst = (tt < T0C)
                        ? ((size_t)b * T0C + tt) * DC + c
                        : (size_t)BB * T0C * DC + ((size_t)b * T1C + (tt - T0C)) * DC + c;
                    float2 v = {v0 + rv.x, v1 + rv.y};
                    *(float2*)&C[dst] = v;
                } else if (MODE == 4) {
                    float2 v = {gelu_tanh(v0), gelu_tanh(v1)};
                    *(float2*)&C[(size_t)r * Nout + c] = v;
                } else {  // MODE 5
                    float2 g = *(const float2*)&C[(size_t)r * Nout + c];
                    float2 v = {v0 * g.x, v1 * g.y};
                    *(float2*)&C[(size_t)r * Nout + c] = v;
                }
            }
        }
    }
}

// ================= elementwise / attention =================
__device__ __forceinline__ float warp_sum(float v) {
    #pragma unroll
    for (int o = 16; o; o >>= 1) v += __shfl_down_sync(0xffffffffu, v, o);
    return v;
}

__global__ void rms_seg_kernel(const float* __restrict__ x0, const float* __restrict__ x1,
                               const float* __restrict__ s0, const float* __restrict__ s1,
                               float* __restrict__ out) {
    int row = blockIdx.x;
    int b = row >> 10, t = row & 1023;
    const float* x; const float* s;
    if (t < T0C) { x = x0 + ((size_t)b*T0C + t)*DC; s = s0; }
    else         { x = x1 + ((size_t)b*T1C + (t - T0C))*DC; s = s1; }
    float ss = 0.f;
    for (int d = threadIdx.x; d < DC; d += 256) { float v = x[d]; ss += v*v; }
    __shared__ float red[8];
    ss = warp_sum(ss);
    if ((threadIdx.x & 31) == 0) red[threadIdx.x >> 5] = ss;
    __syncthreads();
    if (threadIdx.x < 8) {
        float v = red[threadIdx.x];
        #pragma unroll
        for (int o = 4; o; o >>= 1) v += __shfl_down_sync(0xffu, v, o);
        if (threadIdx.x == 0) red[0] = v;
    }
    __syncthreads();
    float inv = rsqrtf(red[0] * (1.f / DC) + 1e-6f);
    float* o = out + (size_t)row * DC;
    for (int d = threadIdx.x; d < DC; d += 256) o[d] = x[d] * inv * (1.f + s[d]);
}

__global__ void rms_cont_kernel(const float* __restrict__ xin,
                                const float* __restrict__ s0, const float* __restrict__ s1,
                                float* __restrict__ out) {
    int row = blockIdx.x;
    int t = row & 1023;
    const float* x = xin + (size_t)row * DC;
    const float* s = (t < T0C) ? s0 : s1;
    float ss = 0.f;
    for (int d = threadIdx.x; d < DC; d += 256) { float v = x[d]; ss += v*v; }
    __shared__ float red[8];
    ss = warp_sum(ss);
    if ((threadIdx.x & 31) == 0) red[threadIdx.x >> 5] = ss;
    __syncthreads();
    if (threadIdx.x < 8) {
        float v = red[threadIdx.x];
        #pragma unroll
        for (int o = 4; o; o >>= 1) v += __shfl_down_sync(0xffu, v, o);
        if (threadIdx.x == 0) red[0] = v;
    }
    __syncthreads();
    float inv = rsqrtf(red[0] * (1.f / DC) + 1e-6f);
    float* o = out + (size_t)row * DC;
    for (int d = threadIdx.x; d < DC; d += 256) o[d] = x[d] * inv * (1.f + s[d]);
}

__global__ void rope_q_kernel(const float* __restrict__ qlin, float* __restrict__ qout) {
    int head = blockIdx.x;
    int bt = head >> 3;
    int t = bt & 1023;
    int i = threadIdx.x;
    float fe = (float)i * (1.f / 128.f);
    float ts = powf(10000.f, fe);
    float rad = (float)t / ts;
    float s, c;
    sincosf(rad, &s, &c);
    size_t base = (size_t)head * HC;
    float x1 = qlin[base + i], x2 = qlin[base + 128 + i];
    const float sc = 0.0625f;
    qout[base + i]       = (x1 * c - x2 * s) * sc;
    qout[base + 128 + i] = (x2 * c + x1 * s) * sc;
}

__global__ void rope_k_kernel(const float* __restrict__ klin, float* __restrict__ kT) {
    int bt = blockIdx.x;
    int b = bt >> 10, t = bt & 1023;
    int i = threadIdx.x;
    float fe = (float)i * (1.f / 128.f);
    float ts = powf(10000.f, fe);
    float rad = (float)t / ts;
    float s, c;
    sincosf(rad, &s, &c);
    size_t base = (size_t)bt * HC;
    float x1 = klin[base + i], x2 = klin[base + 128 + i];
    kT[((size_t)b * HC + i) * TC + t]       = x1 * c - x2 * s;
    kT[((size_t)b * HC + 128 + i) * TC + t] = x2 * c + x1 * s;
}

__global__ void attn_kernel(const float* __restrict__ q, const float* __restrict__ kT,
                            const float* __restrict__ v, float* __restrict__ enc) {
    int qt0 = blockIdx.x * 8;
    int n = blockIdx.y, b = blockIdx.z;
    __shared__ float qs[8][HC];
    __shared__ float sc[8][TC];
    int tid = threadIdx.x;
    for (int idx = tid; idx < 8 * HC; idx += 256) {
        int qi = idx >> 8, h = idx & 255;
        qs[qi][h] = q[(((size_t)b * TC + qt0 + qi) * NQ + n) * HC + h];
    }
    __syncthreads();
    int w = tid >> 5, lane = tid & 31;
    int t = qt0 + w;
    const float* kTb = kT + (size_t)b * HC * TC;
    for (int j = lane; j < TC; j += 32) {
        float s = 0.f;
        #pragma unroll 8
        for (int d = 0; d < HC; d++)
            s += qs[w][d] * kTb[(size_t)d * TC + j];
        bool valid = (j < T0C) || (t >= T0C && j <= t);
        sc[w][j] = valid ? s : NEGC;
    }
    float m = -3.4e38f;
    for (int j = lane; j < TC; j += 32) m = fmaxf(m, sc[w][j]);
    #pragma unroll
    for (int o = 16; o; o >>= 1) m = fmaxf(m, __shfl_xor_sync(0xffffffffu, m, o));
    float l = 0.f;
    for (int j = lane; j < TC; j += 32) {
        float p = expf(sc[w][j] - m);
        sc[w][j] = p;
        l += p;
    }
    #pragma unroll
    for (int o = 16; o; o >>= 1) l += __shfl_xor_sync(0xffffffffu, l, o);
    float linv = 1.f / l;
    __syncwarp();
    float acc[8] = {};
    const float* vb = v + (size_t)b * TC * HC;
    for (int j = 0; j < TC; j++) {
        float p = sc[w][j];
        #pragma unroll
        for (int hh = 0; hh < 8; hh++)
            acc[hh] += p * vb[(size_t)j * HC + lane + 32 * hh];
    }
    #pragma unroll
    for (int hh = 0; hh < 8; hh++)
        enc[(((size_t)b * TC + t) * NQ + n) * HC + lane + 32 * hh] = acc[hh] * linv;
}

// ================= launch =================
extern "C" void kernel_launch(void* const* d_in, const int* in_sizes, int n_in,
                              void* d_out, int out_size) {
    const float* x0  = (const float*)d_in[0];
    const float* x1  = (const float*)d_in[1];
    const float* qw0 = (const float*)d_in[4];
    const float* kw0 = (const float*)d_in[5];
    const float* vw0 = (const float*)d_in[6];
    const float* ow0 = (const float*)d_in[7];
    const float* gw0 = (const float*)d_in[8];
    const float* uw0 = (const float*)d_in[9];
    const float* dw0 = (const float*)d_in[10];
    const float* pa0 = (const float*)d_in[11];
    const float* pf0 = (const float*)d_in[12];
    const float* qw1 = (const float*)d_in[13];
    const float* kw1 = (const float*)d_in[14];
    const float* vw1 = (const float*)d_in[15];
    const float* ow1 = (const float*)d_in[16];
    const float* gw1 = (const float*)d_in[17];
    const float* uw1 = (const float*)d_in[18];
    const float* dw1 = (const float*)d_in[19];
    const float* pa1 = (const float*)d_in[20];
    const float* pf1 = (const float*)d_in[21];

    float *pre, *qlin, *qb, *klin, *kT, *vb, *enc, *resid, *hid, *gu;
    cudaGetSymbolAddress((void**)&pre,   g_pre);
    cudaGetSymbolAddress((void**)&qlin,  g_qlin);
    cudaGetSymbolAddress((void**)&qb,    g_q);
    cudaGetSymbolAddress((void**)&klin,  g_klin);
    cudaGetSymbolAddress((void**)&kT,    g_kT);
    cudaGetSymbolAddress((void**)&vb,    g_v);
    cudaGetSymbolAddress((void**)&enc,   g_enc);
    cudaGetSymbolAddress((void**)&resid, g_resid);
    cudaGetSymbolAddress((void**)&hid,   g_hid);
    cudaGetSymbolAddress((void**)&gu,    g_gu);

    const int SMEM = SSTG * 2 * (int)sizeof(float);   // 73728 bytes
    cudaFuncSetAttribute(mma_gemm<0>, cudaFuncAttributeMaxDynamicSharedMemorySize, SMEM);
    cudaFuncSetAttribute(mma_gemm<1>, cudaFuncAttributeMaxDynamicSharedMemorySize, SMEM);
    cudaFuncSetAttribute(mma_gemm<2>, cudaFuncAttributeMaxDynamicSharedMemorySize, SMEM);
    cudaFuncSetAttribute(mma_gemm<4>, cudaFuncAttributeMaxDynamicSharedMemorySize, SMEM);
    cudaFuncSetAttribute(mma_gemm<5>, cudaFuncAttributeMaxDynamicSharedMemorySize, SMEM);

    // 1. pre = RMSNorm(x)
    rms_seg_kernel<<<BB * TC, 256>>>(x0, x1, pa0, pa1, pre);
    // 2. QKV projections (tensor-core tf32)
    mma_gemm<0><<<dim3(32, 16), 256, SMEM>>>(pre, qw0, qw1, qlin, NHD, DC, nullptr, nullptr, nullptr);
    mma_gemm<0><<<dim3(32, 2),  256, SMEM>>>(pre, kw0, kw1, klin, HC,  DC, nullptr, nullptr, nullptr);
    mma_gemm<0><<<dim3(32, 2),  256, SMEM>>>(pre, vw0, vw1, vb,   HC,  DC, nullptr, nullptr, nullptr);
    // 3. RoPE
    rope_q_kernel<<<BB * TC * NQ, 128>>>(qlin, qb);
    rope_k_kernel<<<BB * TC, 128>>>(klin, kT);
    // 4. attention
    attn_kernel<<<dim3(TC / 8, NQ, BB), 256>>>(qb, kT, vb, enc);
    // 5. O-proj + residual
    mma_gemm<1><<<dim3(32, 16), 256, SMEM>>>(enc, ow0, ow1, resid, DC, NHD, x0, x1, nullptr);
    // 6. hidden = RMSNorm(resid)
    rms_cont_kernel<<<BB * TC, 256>>>(resid, pf0, pf1, hid);
    // 7. gate pass: gu = gelu(hid @ gw.T)
    mma_gemm<4><<<dim3(32, 128), 256, SMEM>>>(hid, gw0, gw1, gu, FC, DC, nullptr, nullptr, nullptr);
    // 8. up pass: gu *= hid @ uw.T
    mma_gemm<5><<<dim3(32, 128), 256, SMEM>>>(hid, uw0, uw1, gu, FC, DC, nullptr, nullptr, nullptr);
    // 9. down-proj + residual, scatter to segmented output
    mma_gemm<2><<<dim3(32, 16), 256, SMEM>>>(gu, dw0, dw1, (float*)d_out, DC, FC, nullptr, nullptr, resid);
}

// round 4
// speedup vs baseline: 2.4467x; 1.0160x over previous
#include <cuda_runtime.h>
#include <cuda_bf16.h>
#include <cstdint>
#include <cstddef>

#define BB 4
#define T0C 256
#define T1C 768
#define TC 1024
#define DC 2048
#define NQ 8
#define HC 256
#define FC 16384
#define NHD 2048
#define QKVW 2560
#define NEGC (-2.3819763e+38f)

// ---------------- static scratch ----------------
__device__ float g_pre  [(size_t)BB*TC*DC];
__device__ float g_qkv  [(size_t)BB*TC*QKVW];
__device__ float g_q    [(size_t)BB*TC*NHD];
__device__ float g_kT   [(size_t)BB*HC*TC];
__device__ float g_enc  [(size_t)BB*TC*NHD];
__device__ float g_resid[(size_t)BB*TC*DC];
__device__ float g_hid  [(size_t)BB*TC*DC];
__device__ float g_gu   [(size_t)BB*TC*FC];

__device__ __forceinline__ uint32_t f2tf32(float f) {
    uint32_t r;
    asm("cvt.rna.tf32.f32 %0, %1;" : "=r"(r) : "f"(f));
    return r;
}
__device__ __forceinline__ uint32_t smem_u32(const void* p) {
    uint32_t a;
    asm("{ .reg .u64 t; cvta.to.shared.u64 t, %1; cvt.u32.u64 %0, t; }" : "=r"(a) : "l"(p));
    return a;
}
__device__ __forceinline__ void cp16(uint32_t dst, const void* src) {
    asm volatile("cp.async.ca.shared.global [%0], [%1], 16;" :: "r"(dst), "l"(src));
}
#define CP_COMMIT() asm volatile("cp.async.commit_group;" ::: "memory")
#define CP_WAIT(n)  asm volatile("cp.async.wait_group %0;" :: "n"(n) : "memory")

__device__ __forceinline__ void mma8(float* d, const uint32_t* a, const uint32_t* b) {
    asm volatile(
        "mma.sync.aligned.m16n8k8.row.col.f32.tf32.tf32.f32 "
        "{%0,%1,%2,%3}, {%4,%5,%6,%7}, {%8,%9}, {%0,%1,%2,%3};"
        : "+f"(d[0]), "+f"(d[1]), "+f"(d[2]), "+f"(d[3])
        : "r"(a[0]), "r"(a[1]), "r"(a[2]), "r"(a[3]), "r"(b[0]), "r"(b[1]));
}

__device__ __forceinline__ float gelu_tanh(float x) {
    float x3 = x * x * x;
    return 0.5f * x * (1.f + tanhf(0.7978845608028654f * (x + 0.044715f * x3)));
}

// ================= cp.async multistage tf32 GEMM =================
// C[4096, Nout] = A[4096, Kdim] @ W.T, weights per 128-row segment.
// MODE 0: store acc                MODE 1: acc + X(seg)   (o-proj + residual)
// MODE 2: acc + Radd -> scattered d_out (down-proj)
// MODE 4: gelu(acc)  (gate)       MODE 5: acc * C  (up, RMW)
// MODE 6: fused QKV (blockIdx.y 0-15 -> qw, 16-17 -> kw, 18-19 -> vw)
#define SROW 20
#define NSTAGE 4
#define STGF (2 * 128 * SROW)          // floats per stage

template <int MODE>
__global__ void __launch_bounds__(256, 2)
mma_gemm(const float* __restrict__ A,
         const float* __restrict__ W0, const float* __restrict__ W1,
         const float* __restrict__ K0, const float* __restrict__ K1,
         const float* __restrict__ V0, const float* __restrict__ V1,
         float* __restrict__ C, int Nout, int Kdim,
         const float* __restrict__ X0, const float* __restrict__ X1,
         const float* __restrict__ Radd) {
    extern __shared__ float smf[];
    uint32_t sbase = smem_u32(smf);
    int tid = threadIdx.x, wid = tid >> 5, lane = tid & 31;
    int warp_m = wid & 3, warp_n = wid >> 2;
    int rm0 = blockIdx.x * 128;
    int rn0 = blockIdx.y * 128;
    bool seg1 = (rm0 & 1023) >= T0C;

    const float* Wa; const float* Wb; int wr0 = rn0;
    if (MODE == 6) {
        if (blockIdx.y < 16)      { Wa = W0; Wb = W1; wr0 = blockIdx.y * 128; }
        else if (blockIdx.y < 18) { Wa = K0; Wb = K1; wr0 = (blockIdx.y - 16) * 128; }
        else                      { Wa = V0; Wb = V1; wr0 = (blockIdx.y - 18) * 128; }
    } else { Wa = W0; Wb = W1; }
    const float* W = seg1 ? Wb : Wa;

    float acc[2][8][4];
    #pragma unroll
    for (int t = 0; t < 2; t++)
        #pragma unroll
        for (int j = 0; j < 8; j++)
            #pragma unroll
            for (int e = 0; e < 4; e++) acc[t][j][e] = 0.f;

    auto issue = [&](int c) {
        int stg = c & (NSTAGE - 1);
        uint32_t sb = sbase + stg * (STGF * 4);
        int kb = c << 4;
        #pragma unroll
        for (int it = 0; it < 4; it++) {
            int idx = it * 256 + tid;
            int row = (idx >> 2) & 127;
            int c4 = (idx & 3) << 2;
            if (idx < 512)
                cp16(sb + (uint32_t)(row * SROW + c4) * 4,
                     A + (size_t)(rm0 + row) * Kdim + kb + c4);
            else
                cp16(sb + (uint32_t)(128 * SROW + row * SROW + c4) * 4,
                     W + (size_t)(wr0 + row) * Kdim + kb + c4);
        }
    };

    auto compute = [&](int stg) {
        const float* As = smf + stg * STGF;
        const float* Ws = As + 128 * SROW;
        int arow = warp_m * 32 + (lane >> 2);
        int brow = warp_n * 64 + (lane >> 2);
        #pragma unroll
        for (int ks = 0; ks < 2; ks++) {
            int ac = ks * 8 + (lane & 3);
            uint32_t af[2][4], bf[8][2];
            #pragma unroll
            for (int t = 0; t < 2; t++) {
                const float* p = &As[(arow + t * 16) * SROW + ac];
                af[t][0] = f2tf32(p[0]);
                af[t][1] = f2tf32(p[8 * SROW]);
                af[t][2] = f2tf32(p[4]);
                af[t][3] = f2tf32(p[8 * SROW + 4]);
            }
            #pragma unroll
            for (int j = 0; j < 8; j++) {
                const float* p = &Ws[(brow + j * 8) * SROW + ac];
                bf[j][0] = f2tf32(p[0]);
                bf[j][1] = f2tf32(p[4]);
            }
            #pragma unroll
            for (int t = 0; t < 2; t++)
                #pragma unroll
                for (int j = 0; j < 8; j++)
                    mma8(acc[t][j], af[t], bf[j]);
        }
    };

    const int nch = Kdim >> 4;
    #pragma unroll
    for (int s = 0; s < NSTAGE - 1; s++) { issue(s); CP_COMMIT(); }
    for (int c = 0; c < nch; c++) {
        CP_WAIT(NSTAGE - 2);
        __syncthreads();
        compute(c & (NSTAGE - 1));
        int nx = c + NSTAGE - 1;
        if (nx < nch) { issue(nx); CP_COMMIT(); }
    }

    // ---------------- epilogue ----------------
    #pragma unroll
    for (int t = 0; t < 2; t++) {
        #pragma unroll
        for (int j = 0; j < 8; j++) {
            int c = rn0 + warp_n * 64 + j * 8 + (lane & 3) * 2;
            #pragma unroll
            for (int h = 0; h < 2; h++) {
                int r = rm0 + warp_m * 32 + t * 16 + (lane >> 2) + h * 8;
                float v0 = acc[t][j][h * 2 + 0];
                float v1 = acc[t][j][h * 2 + 1];
                if (MODE == 0 || MODE == 6) {
                    float2 v = {v0, v1};
                    *(float2*)&C[(size_t)r * Nout + c] = v;
                } else if (MODE == 1) {
                    int b = r >> 10, tt = r & 1023;
                    const float* xp = (tt < T0C)
                        ? X0 + ((size_t)b * T0C + tt) * DC + c
                        : X1 + ((size_t)b * T1C + (tt - T0C)) * DC + c;
                    float2 xv = *(const float2*)xp;
                    float2 v = {v0 + xv.x, v1 + xv.y};
                    *(float2*)&C[(size_t)r * DC + c] = v;
                } else if (MODE == 2) {
                    float2 rv = *(const float2*)&Radd[(size_t)r * DC + c];
                    int b = r >> 10, tt = r & 1023;
                    size_t dst = (tt < T0C)
                        ? ((size_t)b * T0C + tt) * DC + c
                        : (size_t)BB * T0C * DC + ((size_t)b * T1C + (tt - T0C)) * DC + c;
                    float2 v = {v0 + rv.x, v1 + rv.y};
                    *(float2*)&C[dst] = v;
                } else if (MODE == 4) {
                    float2 v = {gelu_tanh(v0), gelu_tanh(v1)};
                    *(float2*)&C[(size_t)r * Nout + c] = v;
                } else {  // MODE 5
                    float2 g = *(const float2*)&C[(size_t)r * Nout + c];
                    float2 v = {v0 * g.x, v1 * g.y};
                    *(float2*)&C[(size_t)r * Nout + c] = v;
                }
            }
        }
    }
}

// ================= elementwise / attention =================
__device__ __forceinline__ float warp_sum(float v) {
    #pragma unroll
    for (int o = 16; o; o >>= 1) v += __shfl_down_sync(0xffffffffu, v, o);
    return v;
}

__global__ void rms_seg_kernel(const float* __restrict__ x0, const float* __restrict__ x1,
                               const float* __restrict__ s0, const float* __restrict__ s1,
                               float* __restrict__ out) {
    int row = blockIdx.x;
    int b = row >> 10, t = row & 1023;
    const float* x; const float* s;
    if (t < T0C) { x = x0 + ((size_t)b*T0C + t)*DC; s = s0; }
    else         { x = x1 + ((size_t)b*T1C + (t - T0C))*DC; s = s1; }
    float ss = 0.f;
    for (int d = threadIdx.x; d < DC; d += 256) { float v = x[d]; ss += v*v; }
    __shared__ float red[8];
    ss = warp_sum(ss);
    if ((threadIdx.x & 31) == 0) red[threadIdx.x >> 5] = ss;
    __syncthreads();
    if (threadIdx.x < 8) {
        float v = red[threadIdx.x];
        #pragma unroll
        for (int o = 4; o; o >>= 1) v += __shfl_down_sync(0xffu, v, o);
        if (threadIdx.x == 0) red[0] = v;
    }
    __syncthreads();
    float inv = rsqrtf(red[0] * (1.f / DC) + 1e-6f);
    float* o = out + (size_t)row * DC;
    for (int d = threadIdx.x; d < DC; d += 256) o[d] = x[d] * inv * (1.f + s[d]);
}

__global__ void rms_cont_kernel(const float* __restrict__ xin,
                                const float* __restrict__ s0, const float* __restrict__ s1,
                                float* __restrict__ out) {
    int row = blockIdx.x;
    int t = row & 1023;
    const float* x = xin + (size_t)row * DC;
    const float* s = (t < T0C) ? s0 : s1;
    float ss = 0.f;
    for (int d = threadIdx.x; d < DC; d += 256) { float v = x[d]; ss += v*v; }
    __shared__ float red[8];
    ss = warp_sum(ss);
    if ((threadIdx.x & 31) == 0) red[threadIdx.x >> 5] = ss;
    __syncthreads();
    if (threadIdx.x < 8) {
        float v = red[threadIdx.x];
        #pragma unroll
        for (int o = 4; o; o >>= 1) v += __shfl_down_sync(0xffu, v, o);
        if (threadIdx.x == 0) red[0] = v;
    }
    __syncthreads();
    float inv = rsqrtf(red[0] * (1.f / DC) + 1e-6f);
    float* o = out + (size_t)row * DC;
    for (int d = threadIdx.x; d < DC; d += 256) o[d] = x[d] * inv * (1.f + s[d]);
}

// q slice of fused qkv -> dense g_q with RoPE + scale
__global__ void rope_q_kernel(const float* __restrict__ qkv, float* __restrict__ qout) {
    int head = blockIdx.x;
    int bt = head >> 3, n = head & 7;
    int t = bt & 1023;
    int i = threadIdx.x;
    float fe = (float)i * (1.f / 128.f);
    float ts = powf(10000.f, fe);
    float rad = (float)t / ts;
    float s, c;
    sincosf(rad, &s, &c);
    size_t base = (size_t)bt * QKVW + (size_t)n * HC;
    float x1 = qkv[base + i], x2 = qkv[base + 128 + i];
    const float sc = 0.0625f;
    size_t ob = (size_t)head * HC;
    qout[ob + i]       = (x1 * c - x2 * s) * sc;
    qout[ob + 128 + i] = (x2 * c + x1 * s) * sc;
}

// k slice of fused qkv -> transposed kT with RoPE
__global__ void rope_k_kernel(const float* __restrict__ qkv, float* __restrict__ kT) {
    int bt = blockIdx.x;
    int b = bt >> 10, t = bt & 1023;
    int i = threadIdx.x;
    float fe = (float)i * (1.f / 128.f);
    float ts = powf(10000.f, fe);
    float rad = (float)t / ts;
    float s, c;
    sincosf(rad, &s, &c);
    size_t base = (size_t)bt * QKVW + NHD;
    float x1 = qkv[base + i], x2 = qkv[base + 128 + i];
    kT[((size_t)b * HC + i) * TC + t]       = x1 * c - x2 * s;
    kT[((size_t)b * HC + 128 + i) * TC + t] = x2 * c + x1 * s;
}

__global__ void attn_kernel(const float* __restrict__ q, const float* __restrict__ kT,
                            const float* __restrict__ qkv, float* __restrict__ enc) {
    int qt0 = blockIdx.x * 8;
    int n = blockIdx.y, b = blockIdx.z;
    __shared__ float qs[8][HC];
    __shared__ float sc[8][TC];
    int tid = threadIdx.x;
    for (int idx = tid; idx < 8 * HC; idx += 256) {
        int qi = idx >> 8, h = idx & 255;
        qs[qi][h] = q[(((size_t)b * TC + qt0 + qi) * NQ + n) * HC + h];
    }
    __syncthreads();
    int w = tid >> 5, lane = tid & 31;
    int t = qt0 + w;
    const float* kTb = kT + (size_t)b * HC * TC;
    for (int j = lane; j < TC; j += 32) {
        float s = 0.f;
        #pragma unroll 8
        for (int d = 0; d < HC; d++)
            s += qs[w][d] * kTb[(size_t)d * TC + j];
        bool valid = (j < T0C) || (t >= T0C && j <= t);
        sc[w][j] = valid ? s : NEGC;
    }
    float m = -3.4e38f;
    for (int j = lane; j < TC; j += 32) m = fmaxf(m, sc[w][j]);
    #pragma unroll
    for (int o = 16; o; o >>= 1) m = fmaxf(m, __shfl_xor_sync(0xffffffffu, m, o));
    float l = 0.f;
    for (int j = lane; j < TC; j += 32) {
        float p = expf(sc[w][j] - m);
        sc[w][j] = p;
        l += p;
    }
    #pragma unroll
    for (int o = 16; o; o >>= 1) l += __shfl_xor_sync(0xffffffffu, l, o);
    float linv = 1.f / l;
    __syncwarp();
    float acc[8] = {};
    const float* vb = qkv + (size_t)b * TC * QKVW + NHD + HC;   // v slice, stride QKVW
    for (int j = 0; j < TC; j++) {
        float p = sc[w][j];
        #pragma unroll
        for (int hh = 0; hh < 8; hh++)
            acc[hh] += p * vb[(size_t)j * QKVW + lane + 32 * hh];
    }
    #pragma unroll
    for (int hh = 0; hh < 8; hh++)
        enc[(((size_t)b * TC + t) * NQ + n) * HC + lane + 32 * hh] = acc[hh] * linv;
}

// ================= launch =================
extern "C" void kernel_launch(void* const* d_in, const int* in_sizes, int n_in,
                              void* d_out, int out_size) {
    const float* x0  = (const float*)d_in[0];
    const float* x1  = (const float*)d_in[1];
    const float* qw0 = (const float*)d_in[4];
    const float* kw0 = (const float*)d_in[5];
    const float* vw0 = (const float*)d_in[6];
    const float* ow0 = (const float*)d_in[7];
    const float* gw0 = (const float*)d_in[8];
    const float* uw0 = (const float*)d_in[9];
    const float* dw0 = (const float*)d_in[10];
    const float* pa0 = (const float*)d_in[11];
    const float* pf0 = (const float*)d_in[12];
    const float* qw1 = (const float*)d_in[13];
    const float* kw1 = (const float*)d_in[14];
    const float* vw1 = (const float*)d_in[15];
    const float* ow1 = (const float*)d_in[16];
    const float* gw1 = (const float*)d_in[17];
    const float* uw1 = (const float*)d_in[18];
    const float* dw1 = (const float*)d_in[19];
    const float* pa1 = (const float*)d_in[20];
    const float* pf1 = (const float*)d_in[21];

    float *pre, *qkv, *qb, *kT, *enc, *resid, *hid, *gu;
    cudaGetSymbolAddress((void**)&pre,   g_pre);
    cudaGetSymbolAddress((void**)&qkv,   g_qkv);
    cudaGetSymbolAddress((void**)&qb,    g_q);
    cudaGetSymbolAddress((void**)&kT,    g_kT);
    cudaGetSymbolAddress((void**)&enc,   g_enc);
    cudaGetSymbolAddress((void**)&resid, g_resid);
    cudaGetSymbolAddress((void**)&hid,   g_hid);
    cudaGetSymbolAddress((void**)&gu,    g_gu);

    const int SMEM = NSTAGE * STGF * (int)sizeof(float);   // 81920
    cudaFuncSetAttribute(mma_gemm<1>, cudaFuncAttributeMaxDynamicSharedMemorySize, SMEM);
    cudaFuncSetAttribute(mma_gemm<2>, cudaFuncAttributeMaxDynamicSharedMemorySize, SMEM);
    cudaFuncSetAttribute(mma_gemm<4>, cudaFuncAttributeMaxDynamicSharedMemorySize, SMEM);
    cudaFuncSetAttribute(mma_gemm<5>, cudaFuncAttributeMaxDynamicSharedMemorySize, SMEM);
    cudaFuncSetAttribute(mma_gemm<6>, cudaFuncAttributeMaxDynamicSharedMemorySize, SMEM);

    // 1. pre = RMSNorm(x)
    rms_seg_kernel<<<BB * TC, 256>>>(x0, x1, pa0, pa1, pre);
    // 2. fused QKV projection -> g_qkv[4096][2560]
    mma_gemm<6><<<dim3(32, 20), 256, SMEM>>>(pre, qw0, qw1, kw0, kw1, vw0, vw1,
                                             qkv, QKVW, DC, nullptr, nullptr, nullptr);
    // 3. RoPE
    rope_q_kernel<<<BB * TC * NQ, 128>>>(qkv, qb);
    rope_k_kernel<<<BB * TC, 128>>>(qkv, kT);
    // 4. attention (v read strided from qkv)
    attn_kernel<<<dim3(TC / 8, NQ, BB), 256>>>(qb, kT, qkv, enc);
    // 5. O-proj + residual
    mma_gemm<1><<<dim3(32, 16), 256, SMEM>>>(enc, ow0, ow1, nullptr, nullptr, nullptr, nullptr,
                                             resid, DC, NHD, x0, x1, nullptr);
    // 6. hidden = RMSNorm(resid)
    rms_cont_kernel<<<BB * TC, 256>>>(resid, pf0, pf1, hid);
    // 7. gate pass: gu = gelu(hid @ gw.T)
    mma_gemm<4><<<dim3(32, 128), 256, SMEM>>>(hid, gw0, gw1, nullptr, nullptr, nullptr, nullptr,
                                              gu, FC, DC, nullptr, nullptr, nullptr);
    // 8. up pass: gu *= hid @ uw.T
    mma_gemm<5><<<dim3(32, 128), 256, SMEM>>>(hid, uw0, uw1, nullptr, nullptr, nullptr, nullptr,
                                              gu, FC, DC, nullptr, nullptr, nullptr);
    // 9. down-proj + residual, scatter to segmented output
    mma_gemm<2><<<dim3(32, 16), 256, SMEM>>>(gu, dw0, dw1, nullptr, nullptr, nullptr, nullptr,
                                             (float*)d_out, DC, FC, nullptr, nullptr, resid);
}

// round 5
// speedup vs baseline: 3.6265x; 1.4822x over previous
#include <cuda_runtime.h>
#include <cuda_bf16.h>
#include <cstdint>
#include <cstddef>

#define BB 4
#define T0C 256
#define T1C 768
#define TC 1024
#define DC 2048
#define NQ 8
#define HC 256
#define FC 16384
#define NHD 2048
#define QKVW 2560
#define MROWS 8192              // per-batch attention rows (T*NQ)
#define NEGC (-2.3819763e+38f)

// ---------------- static scratch ----------------
__device__ float g_pre  [(size_t)BB*TC*DC];
__device__ float g_qkv  [(size_t)BB*TC*QKVW];
__device__ float g_q    [(size_t)BB*TC*NHD];
__device__ float g_kd   [(size_t)BB*TC*HC];      // k dense (b,t,h) with rope
__device__ float g_vT   [(size_t)BB*HC*TC];      // v transposed (b,h,t)
__device__ float g_S    [(size_t)BB*MROWS*TC];   // scores/probs
__device__ float g_enc  [(size_t)BB*TC*NHD];
__device__ float g_resid[(size_t)BB*TC*DC];
__device__ float g_hid  [(size_t)BB*TC*DC];
__device__ float g_gu   [(size_t)BB*TC*FC];

__device__ __forceinline__ uint32_t f2tf32(float f) {
    uint32_t r;
    asm("cvt.rna.tf32.f32 %0, %1;" : "=r"(r) : "f"(f));
    return r;
}
__device__ __forceinline__ uint32_t smem_u32(const void* p) {
    uint32_t a;
    asm("{ .reg .u64 t; cvta.to.shared.u64 t, %1; cvt.u32.u64 %0, t; }" : "=r"(a) : "l"(p));
    return a;
}
__device__ __forceinline__ void cp16(uint32_t dst, const void* src) {
    asm volatile("cp.async.ca.shared.global [%0], [%1], 16;" :: "r"(dst), "l"(src));
}
#define CP_COMMIT() asm volatile("cp.async.commit_group;" ::: "memory")
#define CP_WAIT(n)  asm volatile("cp.async.wait_group %0;" :: "n"(n) : "memory")

__device__ __forceinline__ void mma8(float* d, const uint32_t* a, const uint32_t* b) {
    asm volatile(
        "mma.sync.aligned.m16n8k8.row.col.f32.tf32.tf32.f32 "
        "{%0,%1,%2,%3}, {%4,%5,%6,%7}, {%8,%9}, {%0,%1,%2,%3};"
        : "+f"(d[0]), "+f"(d[1]), "+f"(d[2]), "+f"(d[3])
        : "r"(a[0]), "r"(a[1]), "r"(a[2]), "r"(a[3]), "r"(b[0]), "r"(b[1]));
}

__device__ __forceinline__ float gelu_tanh(float x) {
    float x3 = x * x * x;
    return 0.5f * x * (1.f + tanhf(0.7978845608028654f * (x + 0.044715f * x3)));
}

// ================= cp.async multistage tf32 GEMM =================
// MODE 0: store acc                  MODE 1: acc + X(seg)  (o-proj + residual)
// MODE 2: acc + Radd -> scattered d_out (down-proj)
// MODE 4: gelu(acc)   MODE 5: acc * C (RMW)
// MODE 6: fused QKV (blockIdx.y: 0-15 qw, 16-17 kw, 18-19 vw)
// MODE 7: attention scores + mask (blockIdx.z = batch)
// MODE 8: probs @ vT -> enc        (blockIdx.z = batch)
#define SROW 36
#define NSTAGE 3
#define STGF (2 * 128 * SROW)          // floats per stage

template <int MODE>
__global__ void __launch_bounds__(256, 2)
mma_gemm(const float* __restrict__ A,
         const float* __restrict__ W0, const float* __restrict__ W1,
         const float* __restrict__ K0, const float* __restrict__ K1,
         const float* __restrict__ V0, const float* __restrict__ V1,
         float* __restrict__ C, int Nout, int Kdim,
         const float* __restrict__ X0, const float* __restrict__ X1,
         const float* __restrict__ Radd) {
    extern __shared__ float smf[];
    uint32_t sbase = smem_u32(smf);
    int tid = threadIdx.x, wid = tid >> 5, lane = tid & 31;
    int warp_m = wid & 3, warp_n = wid >> 2;
    int rm0 = blockIdx.x * 128;
    int rn0 = blockIdx.y * 128;
    int z = blockIdx.z;

    const float* Wa; const float* Wb; int wr0 = rn0;
    if (MODE == 6) {
        if (blockIdx.y < 16)      { Wa = W0; Wb = W1; wr0 = blockIdx.y * 128; }
        else if (blockIdx.y < 18) { Wa = K0; Wb = K1; wr0 = (blockIdx.y - 16) * 128; }
        else                      { Wa = V0; Wb = V1; wr0 = (blockIdx.y - 18) * 128; }
    } else { Wa = W0; Wb = W1; }

    const float* W;
    if (MODE == 7) {
        A += (size_t)z * MROWS * HC;
        W = W0 + (size_t)z * TC * HC;
        C += (size_t)z * MROWS * TC;
    } else if (MODE == 8) {
        A += (size_t)z * MROWS * TC;
        W = W0 + (size_t)z * HC * TC;
        C += (size_t)z * MROWS * HC;
    } else {
        W = ((rm0 & 1023) < T0C) ? Wa : Wb;
        if ((rm0 & 1023) >= T0C) W = Wb; else W = Wa;
    }

    float acc[2][8][4];
    #pragma unroll
    for (int t = 0; t < 2; t++)
        #pragma unroll
        for (int j = 0; j < 8; j++)
            #pragma unroll
            for (int e = 0; e < 4; e++) acc[t][j][e] = 0.f;

    auto issue = [&](int c) {
        int stg = c - (c / NSTAGE) * NSTAGE;
        uint32_t sb = sbase + stg * (STGF * 4);
        int kb = c << 5;
        #pragma unroll
        for (int it = 0; it < 8; it++) {
            int idx = it * 256 + tid;
            int row = (idx >> 3) & 127;
            int c4 = (idx & 7) << 2;
            if (idx < 1024)
                cp16(sb + (uint32_t)(row * SROW + c4) * 4,
                     A + (size_t)(rm0 + row) * Kdim + kb + c4);
            else
                cp16(sb + (uint32_t)(128 * SROW + row * SROW + c4) * 4,
                     W + (size_t)(wr0 + row) * Kdim + kb + c4);
        }
    };

    auto compute = [&](int stg) {
        const float* As = smf + stg * STGF;
        const float* Ws = As + 128 * SROW;
        int arow = warp_m * 32 + (lane >> 2);
        int brow = warp_n * 64 + (lane >> 2);
        #pragma unroll
        for (int ks = 0; ks < 4; ks++) {
            int ac = ks * 8 + (lane & 3);
            uint32_t af[2][4], bf[8][2];
            #pragma unroll
            for (int t = 0; t < 2; t++) {
                const float* p = &As[(arow + t * 16) * SROW + ac];
                af[t][0] = f2tf32(p[0]);
                af[t][1] = f2tf32(p[8 * SROW]);
                af[t][2] = f2tf32(p[4]);
                af[t][3] = f2tf32(p[8 * SROW + 4]);
            }
            #pragma unroll
            for (int j = 0; j < 8; j++) {
                const float* p = &Ws[(brow + j * 8) * SROW + ac];
                bf[j][0] = f2tf32(p[0]);
                bf[j][1] = f2tf32(p[4]);
            }
            #pragma unroll
            for (int t = 0; t < 2; t++)
                #pragma unroll
                for (int j = 0; j < 8; j++)
                    mma8(acc[t][j], af[t], bf[j]);
        }
    };

    const int nch = Kdim >> 5;
    issue(0); CP_COMMIT();
    issue(1); CP_COMMIT();
    int stg = 0;
    for (int c = 0; c < nch; c++) {
        CP_WAIT(1);
        __syncthreads();
        compute(stg);
        if (++stg == NSTAGE) stg = 0;
        int nx = c + NSTAGE - 1;
        if (nx < nch) { issue(nx); CP_COMMIT(); }
        __syncthreads();
    }

    // ---------------- epilogue ----------------
    #pragma unroll
    for (int t = 0; t < 2; t++) {
        #pragma unroll
        for (int j = 0; j < 8; j++) {
            int c = rn0 + warp_n * 64 + j * 8 + (lane & 3) * 2;
            #pragma unroll
            for (int h = 0; h < 2; h++) {
                int r = rm0 + warp_m * 32 + t * 16 + (lane >> 2) + h * 8;
                float v0 = acc[t][j][h * 2 + 0];
                float v1 = acc[t][j][h * 2 + 1];
                if (MODE == 0 || MODE == 6) {
                    float2 v = {v0, v1};
                    *(float2*)&C[(size_t)r * Nout + c] = v;
                } else if (MODE == 1) {
                    int b = r >> 10, tt = r & 1023;
                    const float* xp = (tt < T0C)
                        ? X0 + ((size_t)b * T0C + tt) * DC + c
                        : X1 + ((size_t)b * T1C + (tt - T0C)) * DC + c;
                    float2 xv = *(const float2*)xp;
                    float2 v = {v0 + xv.x, v1 + xv.y};
                    *(float2*)&C[(size_t)r * DC + c] = v;
                } else if (MODE == 2) {
                    float2 rv = *(const float2*)&Radd[(size_t)r * DC + c];
                    int b = r >> 10, tt = r & 1023;
                    size_t dst = (tt < T0C)
                        ? ((size_t)b * T0C + tt) * DC + c
                        : (size_t)BB * T0C * DC + ((size_t)b * T1C + (tt - T0C)) * DC + c;
                    float2 v = {v0 + rv.x, v1 + rv.y};
                    *(float2*)&C[dst] = v;
                } else if (MODE == 4) {
                    float2 v = {gelu_tanh(v0), gelu_tanh(v1)};
                    *(float2*)&C[(size_t)r * Nout + c] = v;
                } else if (MODE == 5) {
                    float2 g = *(const float2*)&C[(size_t)r * Nout + c];
                    float2 v = {v0 * g.x, v1 * g.y};
                    *(float2*)&C[(size_t)r * Nout + c] = v;
                } else if (MODE == 7) {
                    int tt = r >> 3;                       // query time
                    float2 v;
                    v.x = ((c < T0C) || (c <= tt)) ? v0 : NEGC;
                    v.y = ((c + 1 < T0C) || (c + 1 <= tt)) ? v1 : NEGC;
                    *(float2*)&C[(size_t)r * TC + c] = v;
                } else {  // MODE 8
                    float2 v = {v0, v1};
                    *(float2*)&C[(size_t)r * HC + c] = v;
                }
            }
        }
    }
}

// ================= elementwise =================
__device__ __forceinline__ float warp_sum(float v) {
    #pragma unroll
    for (int o = 16; o; o >>= 1) v += __shfl_down_sync(0xffffffffu, v, o);
    return v;
}

__global__ void rms_seg_kernel(const float* __restrict__ x0, const float* __restrict__ x1,
                               const float* __restrict__ s0, const float* __restrict__ s1,
                               float* __restrict__ out) {
    int row = blockIdx.x;
    int b = row >> 10, t = row & 1023;
    const float* x; const float* s;
    if (t < T0C) { x = x0 + ((size_t)b*T0C + t)*DC; s = s0; }
    else         { x = x1 + ((size_t)b*T1C + (t - T0C))*DC; s = s1; }
    float ss = 0.f;
    for (int d = threadIdx.x; d < DC; d += 256) { float v = x[d]; ss += v*v; }
    __shared__ float red[8];
    ss = warp_sum(ss);
    if ((threadIdx.x & 31) == 0) red[threadIdx.x >> 5] = ss;
    __syncthreads();
    if (threadIdx.x < 8) {
        float v = red[threadIdx.x];
        #pragma unroll
        for (int o = 4; o; o >>= 1) v += __shfl_down_sync(0xffu, v, o);
        if (threadIdx.x == 0) red[0] = v;
    }
    __syncthreads();
    float inv = rsqrtf(red[0] * (1.f / DC) + 1e-6f);
    float* o = out + (size_t)row * DC;
    for (int d = threadIdx.x; d < DC; d += 256) o[d] = x[d] * inv * (1.f + s[d]);
}

__global__ void rms_cont_kernel(const float* __restrict__ xin,
                                const float* __restrict__ s0, const float* __restrict__ s1,
                                float* __restrict__ out) {
    int row = blockIdx.x;
    int t = row & 1023;
    const float* x = xin + (size_t)row * DC;
    const float* s = (t < T0C) ? s0 : s1;
    float ss = 0.f;
    for (int d = threadIdx.x; d < DC; d += 256) { float v = x[d]; ss += v*v; }
    __shared__ float red[8];
    ss = warp_sum(ss);
    if ((threadIdx.x & 31) == 0) red[threadIdx.x >> 5] = ss;
    __syncthreads();
    if (threadIdx.x < 8) {
        float v = red[threadIdx.x];
        #pragma unroll
        for (int o = 4; o; o >>= 1) v += __shfl_down_sync(0xffu, v, o);
        if (threadIdx.x == 0) red[0] = v;
    }
    __syncthreads();
    float inv = rsqrtf(red[0] * (1.f / DC) + 1e-6f);
    float* o = out + (size_t)row * DC;
    for (int d = threadIdx.x; d < DC; d += 256) o[d] = x[d] * inv * (1.f + s[d]);
}

// q slice of fused qkv -> dense g_q with RoPE + scale
__global__ void rope_q_kernel(const float* __restrict__ qkv, float* __restrict__ qout) {
    int head = blockIdx.x;
    int bt = head >> 3, n = head & 7;
    int t = bt & 1023;
    int i = threadIdx.x;
    float fe = (float)i * (1.f / 128.f);
    float ts = powf(10000.f, fe);
    float rad = (float)t / ts;
    float s, c;
    sincosf(rad, &s, &c);
    size_t base = (size_t)bt * QKVW + (size_t)n * HC;
    float x1 = qkv[base + i], x2 = qkv[base + 128 + i];
    const float sc = 0.0625f;
    size_t ob = (size_t)head * HC;
    qout[ob + i]       = (x1 * c - x2 * s) * sc;
    qout[ob + 128 + i] = (x2 * c + x1 * s) * sc;
}

// k slice of fused qkv -> dense kd (b,t,h) with RoPE
__global__ void rope_k_kernel(const float* __restrict__ qkv, float* __restrict__ kd) {
    int bt = blockIdx.x;
    int t = bt & 1023;
    int i = threadIdx.x;
    float fe = (float)i * (1.f / 128.f);
    float ts = powf(10000.f, fe);
    float rad = (float)t / ts;
    float s, c;
    sincosf(rad, &s, &c);
    size_t base = (size_t)bt * QKVW + NHD;
    float x1 = qkv[base + i], x2 = qkv[base + 128 + i];
    size_t ob = (size_t)bt * HC;
    kd[ob + i]       = x1 * c - x2 * s;
    kd[ob + 128 + i] = x2 * c + x1 * s;
}

// v slice of qkv (b,t,h) -> vT (b,h,t)  (32x32 smem tiles)
__global__ void vT_kernel(const float* __restrict__ qkv, float* __restrict__ vT) {
    __shared__ float tile[32][33];
    int b = blockIdx.z;
    int t0 = blockIdx.x * 32, h0 = blockIdx.y * 32;
    int tx = threadIdx.x, ty = threadIdx.y;       // (32, 8)
    #pragma unroll
    for (int i = 0; i < 4; i++) {
        int t = t0 + ty + i * 8;
        tile[ty + i * 8][tx] = qkv[((size_t)b * TC + t) * QKVW + NHD + HC + h0 + tx];
    }
    __syncthreads();
    #pragma unroll
    for (int i = 0; i < 4; i++) {
        int h = h0 + ty + i * 8;
        vT[((size_t)b * HC + h) * TC + t0 + tx] = tile[tx][ty + i * 8];
    }
}

// row softmax over S[32768][1024]
__global__ void softmax_kernel(float* __restrict__ S) {
    float* row = S + (size_t)blockIdx.x * TC;
    int tid = threadIdx.x;                         // 128 threads
    float4 v[2];
    v[0] = *(float4*)&row[tid * 4];
    v[1] = *(float4*)&row[512 + tid * 4];
    float m = fmaxf(fmaxf(v[0].x, v[0].y), fmaxf(v[0].z, v[0].w));
    m = fmaxf(m, fmaxf(fmaxf(v[1].x, v[1].y), fmaxf(v[1].z, v[1].w)));
    __shared__ float red[4];
    #pragma unroll
    for (int o = 16; o; o >>= 1) m = fmaxf(m, __shfl_xor_sync(0xffffffffu, m, o));
    if ((tid & 31) == 0) red[tid >> 5] = m;
    __syncthreads();
    m = fmaxf(fmaxf(red[0], red[1]), fmaxf(red[2], red[3]));
    float l = 0.f;
    #pragma unroll
    for (int q = 0; q < 2; q++) {
        float* e = &v[q].x;
        #pragma unroll
        for (int i = 0; i < 4; i++) {
            float p = __expf(fmaxf(e[i] - m, -80.f));
            e[i] = p;
            l += p;
        }
    }
    #pragma unroll
    for (int o = 16; o; o >>= 1) l += __shfl_xor_sync(0xffffffffu, l, o);
    if ((tid & 31) == 0) red[tid >> 5] = l;
    __syncthreads();
    l = red[0] + red[1] + red[2] + red[3];
    float inv = 1.f / l;
    #pragma unroll
    for (int q = 0; q < 2; q++) {
        v[q].x *= inv; v[q].y *= inv; v[q].z *= inv; v[q].w *= inv;
    }
    *(float4*)&row[tid * 4] = v[0];
    *(float4*)&row[512 + tid * 4] = v[1];
}

// ================= launch =================
extern "C" void kernel_launch(void* const* d_in, const int* in_sizes, int n_in,
                              void* d_out, int out_size) {
    const float* x0  = (const float*)d_in[0];
    const float* x1  = (const float*)d_in[1];
    const float* qw0 = (const float*)d_in[4];
    const float* kw0 = (const float*)d_in[5];
    const float* vw0 = (const float*)d_in[6];
    const float* ow0 = (const float*)d_in[7];
    const float* gw0 = (const float*)d_in[8];
    const float* uw0 = (const float*)d_in[9];
    const float* dw0 = (const float*)d_in[10];
    const float* pa0 = (const float*)d_in[11];
    const float* pf0 = (const float*)d_in[12];
    const float* qw1 = (const float*)d_in[13];
    const float* kw1 = (const float*)d_in[14];
    const float* vw1 = (const float*)d_in[15];
    const float* ow1 = (const float*)d_in[16];
    const float* gw1 = (const float*)d_in[17];
    const float* uw1 = (const float*)d_in[18];
    const float* dw1 = (const float*)d_in[19];
    const float* pa1 = (const float*)d_in[20];
    const float* pf1 = (const float*)d_in[21];

    float *pre, *qkv, *qb, *kd, *vT, *S, *enc, *resid, *hid, *gu;
    cudaGetSymbolAddress((void**)&pre,   g_pre);
    cudaGetSymbolAddress((void**)&qkv,   g_qkv);
    cudaGetSymbolAddress((void**)&qb,    g_q);
    cudaGetSymbolAddress((void**)&kd,    g_kd);
    cudaGetSymbolAddress((void**)&vT,    g_vT);
    cudaGetSymbolAddress((void**)&S,     g_S);
    cudaGetSymbolAddress((void**)&enc,   g_enc);
    cudaGetSymbolAddress((void**)&resid, g_resid);
    cudaGetSymbolAddress((void**)&hid,   g_hid);
    cudaGetSymbolAddress((void**)&gu,    g_gu);

    const int SMEM = NSTAGE * STGF * (int)sizeof(float);   // 110592
    cudaFuncSetAttribute(mma_gemm<1>, cudaFuncAttributeMaxDynamicSharedMemorySize, SMEM);
    cudaFuncSetAttribute(mma_gemm<2>, cudaFuncAttributeMaxDynamicSharedMemorySize, SMEM);
    cudaFuncSetAttribute(mma_gemm<4>, cudaFuncAttributeMaxDynamicSharedMemorySize, SMEM);
    cudaFuncSetAttribute(mma_gemm<5>, cudaFuncAttributeMaxDynamicSharedMemorySize, SMEM);
    cudaFuncSetAttribute(mma_gemm<6>, cudaFuncAttributeMaxDynamicSharedMemorySize, SMEM);
    cudaFuncSetAttribute(mma_gemm<7>, cudaFuncAttributeMaxDynamicSharedMemorySize, SMEM);
    cudaFuncSetAttribute(mma_gemm<8>, cudaFuncAttributeMaxDynamicSharedMemorySize, SMEM);

    // 1. pre = RMSNorm(x)
    rms_seg_kernel<<<BB * TC, 256>>>(x0, x1, pa0, pa1, pre);
    // 2. fused QKV projection
    mma_gemm<6><<<dim3(32, 20), 256, SMEM>>>(pre, qw0, qw1, kw0, kw1, vw0, vw1,
                                             qkv, QKVW, DC, nullptr, nullptr, nullptr);
    // 3. RoPE + v transpose
    rope_q_kernel<<<BB * TC * NQ, 128>>>(qkv, qb);
    rope_k_kernel<<<BB * TC, 128>>>(qkv, kd);
    vT_kernel<<<dim3(TC / 32, HC / 32, BB), dim3(32, 8)>>>(qkv, vT);
    // 4a. scores = q @ kd.T  (+mask)
    mma_gemm<7><<<dim3(MROWS / 128, TC / 128, BB), 256, SMEM>>>(
        qb, kd, nullptr, nullptr, nullptr, nullptr, nullptr,
        S, TC, HC, nullptr, nullptr, nullptr);
    // 4b. softmax rows
    softmax_kernel<<<BB * MROWS, 128>>>(S);
    // 4c. enc = probs @ vT.T
    mma_gemm<8><<<dim3(MROWS / 128, HC / 128, BB), 256, SMEM>>>(
        S, vT, nullptr, nullptr, nullptr, nullptr, nullptr,
        enc, HC, TC, nullptr, nullptr, nullptr);
    // 5. O-proj + residual
    mma_gemm<1><<<dim3(32, 16), 256, SMEM>>>(enc, ow0, ow1, nullptr, nullptr, nullptr, nullptr,
                                             resid, DC, NHD, x0, x1, nullptr);
    // 6. hidden = RMSNorm(resid)
    rms_cont_kernel<<<BB * TC, 256>>>(resid, pf0, pf1, hid);
    // 7. gate: gu = gelu(hid @ gw.T)
    mma_gemm<4><<<dim3(32, 128), 256, SMEM>>>(hid, gw0, gw1, nullptr, nullptr, nullptr, nullptr,
                                              gu, FC, DC, nullptr, nullptr, nullptr);
    // 8. up: gu *= hid @ uw.T
    mma_gemm<5><<<dim3(32, 128), 256, SMEM>>>(hid, uw0, uw1, nullptr, nullptr, nullptr, nullptr,
                                              gu, FC, DC, nullptr, nullptr, nullptr);
    // 9. down-proj + residual -> segmented d_out
    mma_gemm<2><<<dim3(32, 16), 256, SMEM>>>(gu, dw0, dw1, nullptr, nullptr, nullptr, nullptr,
                                             (float*)d_out, DC, FC, nullptr, nullptr, resid);
}

// round 6
// speedup vs baseline: 3.6711x; 1.0123x over previous
#include <cuda_runtime.h>
#include <cuda_bf16.h>
#include <cstdint>
#include <cstddef>

#define BB 4
#define T0C 256
#define T1C 768
#define TC 1024
#define DC 2048
#define NQ 8
#define HC 256
#define FC 16384
#define NHD 2048
#define QKVW 2560
#define MROWS 8192              // per-batch attention rows (T*NQ)
#define NEGC (-2.3819763e+38f)

// ---------------- static scratch ----------------
__device__ float g_pre  [(size_t)BB*TC*DC];
__device__ float g_qkv  [(size_t)BB*TC*QKVW];
__device__ float g_q    [(size_t)BB*TC*NHD];
__device__ float g_kd   [(size_t)BB*TC*HC];      // k dense (b,t,h) with rope
__device__ float g_vT   [(size_t)BB*HC*TC];      // v transposed (b,h,t)
__device__ float g_S    [(size_t)BB*MROWS*TC];   // scores/probs
__device__ float g_enc  [(size_t)BB*TC*NHD];
__device__ float g_resid[(size_t)BB*TC*DC];
__device__ float g_hid  [(size_t)BB*TC*DC];
__device__ float g_gu   [(size_t)BB*TC*FC];

__device__ __forceinline__ uint32_t f2tf32(float f) {
    uint32_t r;
    asm("cvt.rna.tf32.f32 %0, %1;" : "=r"(r) : "f"(f));
    return r;
}
__device__ __forceinline__ uint32_t smem_u32(const void* p) {
    uint32_t a;
    asm("{ .reg .u64 t; cvta.to.shared.u64 t, %1; cvt.u32.u64 %0, t; }" : "=r"(a) : "l"(p));
    return a;
}
__device__ __forceinline__ void cp16(uint32_t dst, const void* src) {
    asm volatile("cp.async.ca.shared.global [%0], [%1], 16;" :: "r"(dst), "l"(src));
}
#define CP_COMMIT() asm volatile("cp.async.commit_group;" ::: "memory")
#define CP_WAIT(n)  asm volatile("cp.async.wait_group %0;" :: "n"(n) : "memory")

__device__ __forceinline__ void mma8(float* d, const uint32_t* a, const uint32_t* b) {
    asm volatile(
        "mma.sync.aligned.m16n8k8.row.col.f32.tf32.tf32.f32 "
        "{%0,%1,%2,%3}, {%4,%5,%6,%7}, {%8,%9}, {%0,%1,%2,%3};"
        : "+f"(d[0]), "+f"(d[1]), "+f"(d[2]), "+f"(d[3])
        : "r"(a[0]), "r"(a[1]), "r"(a[2]), "r"(a[3]), "r"(b[0]), "r"(b[1]));
}

__device__ __forceinline__ float gelu_tanh(float x) {
    float x3 = x * x * x;
    return 0.5f * x * (1.f + tanhf(0.7978845608028654f * (x + 0.044715f * x3)));
}

// ================= cp.async multistage tf32 GEMM =================
// CTA tile 128x128, 4 warps of 64x64 each (2x2 layout), K-chunk 32.
// MODE 0: store acc                  MODE 1: acc + X(seg)  (o-proj + residual)
// MODE 2: acc + Radd -> scattered d_out (down-proj)
// MODE 4: gelu(acc)   MODE 5: acc * C (RMW)
// MODE 6: fused QKV (blockIdx.y: 0-15 qw, 16-17 kw, 18-19 vw)
// MODE 7: attention scores + mask (blockIdx.z = batch)
// MODE 8: probs @ vT -> enc        (blockIdx.z = batch)
#define SROW 36
#define NSTAGE 3
#define STGF (2 * 128 * SROW)          // floats per stage

template <int MODE>
__global__ void __launch_bounds__(128, 2)
mma_gemm(const float* __restrict__ A,
         const float* __restrict__ W0, const float* __restrict__ W1,
         const float* __restrict__ K0, const float* __restrict__ K1,
         const float* __restrict__ V0, const float* __restrict__ V1,
         float* __restrict__ C, int Nout, int Kdim,
         const float* __restrict__ X0, const float* __restrict__ X1,
         const float* __restrict__ Radd) {
    extern __shared__ float smf[];
    uint32_t sbase = smem_u32(smf);
    int tid = threadIdx.x, wid = tid >> 5, lane = tid & 31;
    int warp_m = wid & 1, warp_n = wid >> 1;      // 2x2 warps, 64x64 each
    int rm0 = blockIdx.x * 128;
    int rn0 = blockIdx.y * 128;
    int z = blockIdx.z;

    const float* Wa; const float* Wb; int wr0 = rn0;
    if (MODE == 6) {
        if (blockIdx.y < 16)      { Wa = W0; Wb = W1; wr0 = blockIdx.y * 128; }
        else if (blockIdx.y < 18) { Wa = K0; Wb = K1; wr0 = (blockIdx.y - 16) * 128; }
        else                      { Wa = V0; Wb = V1; wr0 = (blockIdx.y - 18) * 128; }
    } else { Wa = W0; Wb = W1; }

    const float* W;
    if (MODE == 7) {
        A += (size_t)z * MROWS * HC;
        W = W0 + (size_t)z * TC * HC;
        C += (size_t)z * MROWS * TC;
    } else if (MODE == 8) {
        A += (size_t)z * MROWS * TC;
        W = W0 + (size_t)z * HC * TC;
        C += (size_t)z * MROWS * HC;
    } else {
        W = ((rm0 & 1023) < T0C) ? Wa : Wb;
    }

    float acc[4][8][4];
    #pragma unroll
    for (int t = 0; t < 4; t++)
        #pragma unroll
        for (int j = 0; j < 8; j++)
            #pragma unroll
            for (int e = 0; e < 4; e++) acc[t][j][e] = 0.f;

    auto issue = [&](int c) {
        int stg = c - (c / NSTAGE) * NSTAGE;
        uint32_t sb = sbase + stg * (STGF * 4);
        int kb = c << 5;
        #pragma unroll
        for (int it = 0; it < 16; it++) {
            int idx = it * 128 + tid;
            int row = (idx >> 3) & 127;
            int c4 = (idx & 7) << 2;
            if (idx < 1024)
                cp16(sb + (uint32_t)(row * SROW + c4) * 4,
                     A + (size_t)(rm0 + row) * Kdim + kb + c4);
            else
                cp16(sb + (uint32_t)(128 * SROW + row * SROW + c4) * 4,
                     W + (size_t)(wr0 + row) * Kdim + kb + c4);
        }
    };

    auto compute = [&](int stg) {
        const float* As = smf + stg * STGF;
        const float* Ws = As + 128 * SROW;
        int arow = warp_m * 64 + (lane >> 2);
        int brow = warp_n * 64 + (lane >> 2);
        #pragma unroll
        for (int ks = 0; ks < 4; ks++) {
            int ac = ks * 8 + (lane & 3);
            uint32_t af[4][4], bf[8][2];
            #pragma unroll
            for (int t = 0; t < 4; t++) {
                const float* p = &As[(arow + t * 16) * SROW + ac];
                af[t][0] = f2tf32(p[0]);
                af[t][1] = f2tf32(p[8 * SROW]);
                af[t][2] = f2tf32(p[4]);
                af[t][3] = f2tf32(p[8 * SROW + 4]);
            }
            #pragma unroll
            for (int j = 0; j < 8; j++) {
                const float* p = &Ws[(brow + j * 8) * SROW + ac];
                bf[j][0] = f2tf32(p[0]);
                bf[j][1] = f2tf32(p[4]);
            }
            #pragma unroll
            for (int t = 0; t < 4; t++)
                #pragma unroll
                for (int j = 0; j < 8; j++)
                    mma8(acc[t][j], af[t], bf[j]);
        }
    };

    const int nch = Kdim >> 5;
    issue(0); CP_COMMIT();
    issue(1); CP_COMMIT();
    int stg = 0;
    for (int c = 0; c < nch; c++) {
        CP_WAIT(1);
        __syncthreads();
        compute(stg);
        if (++stg == NSTAGE) stg = 0;
        int nx = c + NSTAGE - 1;
        if (nx < nch) { issue(nx); CP_COMMIT(); }
        __syncthreads();
    }

    // ---------------- epilogue ----------------
    #pragma unroll
    for (int t = 0; t < 4; t++) {
        #pragma unroll
        for (int j = 0; j < 8; j++) {
            int c = rn0 + warp_n * 64 + j * 8 + (lane & 3) * 2;
            #pragma unroll
            for (int h = 0; h < 2; h++) {
                int r = rm0 + warp_m * 64 + t * 16 + (lane >> 2) + h * 8;
                float v0 = acc[t][j][h * 2 + 0];
                float v1 = acc[t][j][h * 2 + 1];
                if (MODE == 0 || MODE == 6) {
                    float2 v = {v0, v1};
                    *(float2*)&C[(size_t)r * Nout + c] = v;
                } else if (MODE == 1) {
                    int b = r >> 10, tt = r & 1023;
                    const float* xp = (tt < T0C)
                        ? X0 + ((size_t)b * T0C + tt) * DC + c
                        : X1 + ((size_t)b * T1C + (tt - T0C)) * DC + c;
                    float2 xv = *(const float2*)xp;
                    float2 v = {v0 + xv.x, v1 + xv.y};
                    *(float2*)&C[(size_t)r * DC + c] = v;
                } else if (MODE == 2) {
                    float2 rv = *(const float2*)&Radd[(size_t)r * DC + c];
                    int b = r >> 10, tt = r & 1023;
                    size_t dst = (tt < T0C)
                        ? ((size_t)b * T0C + tt) * DC + c
                        : (size_t)BB * T0C * DC + ((size_t)b * T1C + (tt - T0C)) * DC + c;
                    float2 v = {v0 + rv.x, v1 + rv.y};
                    *(float2*)&C[dst] = v;
                } else if (MODE == 4) {
                    float2 v = {gelu_tanh(v0), gelu_tanh(v1)};
                    *(float2*)&C[(size_t)r * Nout + c] = v;
                } else if (MODE == 5) {
                    float2 g = *(const float2*)&C[(size_t)r * Nout + c];
                    float2 v = {v0 * g.x, v1 * g.y};
                    *(float2*)&C[(size_t)r * Nout + c] = v;
                } else if (MODE == 7) {
                    int tt = r >> 3;                       // query time
                    float2 v;
                    v.x = ((c < T0C) || (c <= tt)) ? v0 : NEGC;
                    v.y = ((c + 1 < T0C) || (c + 1 <= tt)) ? v1 : NEGC;
                    *(float2*)&C[(size_t)r * TC + c] = v;
                } else {  // MODE 8
                    float2 v = {v0, v1};
                    *(float2*)&C[(size_t)r * HC + c] = v;
                }
            }
        }
    }
}

// ================= elementwise =================
__device__ __forceinline__ float warp_sum(float v) {
    #pragma unroll
    for (int o = 16; o; o >>= 1) v += __shfl_down_sync(0xffffffffu, v, o);
    return v;
}

__global__ void rms_seg_kernel(const float* __restrict__ x0, const float* __restrict__ x1,
                               const float* __restrict__ s0, const float* __restrict__ s1,
                               float* __restrict__ out) {
    int row = blockIdx.x;
    int b = row >> 10, t = row & 1023;
    const float* x; const float* s;
    if (t < T0C) { x = x0 + ((size_t)b*T0C + t)*DC; s = s0; }
    else         { x = x1 + ((size_t)b*T1C + (t - T0C))*DC; s = s1; }
    float ss = 0.f;
    for (int d = threadIdx.x; d < DC; d += 256) { float v = x[d]; ss += v*v; }
    __shared__ float red[8];
    ss = warp_sum(ss);
    if ((threadIdx.x & 31) == 0) red[threadIdx.x >> 5] = ss;
    __syncthreads();
    if (threadIdx.x < 8) {
        float v = red[threadIdx.x];
        #pragma unroll
        for (int o = 4; o; o >>= 1) v += __shfl_down_sync(0xffu, v, o);
        if (threadIdx.x == 0) red[0] = v;
    }
    __syncthreads();
    float inv = rsqrtf(red[0] * (1.f / DC) + 1e-6f);
    float* o = out + (size_t)row * DC;
    for (int d = threadIdx.x; d < DC; d += 256) o[d] = x[d] * inv * (1.f + s[d]);
}

__global__ void rms_cont_kernel(const float* __restrict__ xin,
                                const float* __restrict__ s0, const float* __restrict__ s1,
                                float* __restrict__ out) {
    int row = blockIdx.x;
    int t = row & 1023;
    const float* x = xin + (size_t)row * DC;
    const float* s = (t < T0C) ? s0 : s1;
    float ss = 0.f;
    for (int d = threadIdx.x; d < DC; d += 256) { float v = x[d]; ss += v*v; }
    __shared__ float red[8];
    ss = warp_sum(ss);
    if ((threadIdx.x & 31) == 0) red[threadIdx.x >> 5] = ss;
    __syncthreads();
    if (threadIdx.x < 8) {
        float v = red[threadIdx.x];
        #pragma unroll
        for (int o = 4; o; o >>= 1) v += __shfl_down_sync(0xffu, v, o);
        if (threadIdx.x == 0) red[0] = v;
    }
    __syncthreads();
    float inv = rsqrtf(red[0] * (1.f / DC) + 1e-6f);
    float* o = out + (size_t)row * DC;
    for (int d = threadIdx.x; d < DC; d += 256) o[d] = x[d] * inv * (1.f + s[d]);
}

// q slice of fused qkv -> dense g_q with RoPE + scale
__global__ void rope_q_kernel(const float* __restrict__ qkv, float* __restrict__ qout) {
    int head = blockIdx.x;
    int bt = head >> 3, n = head & 7;
    int t = bt & 1023;
    int i = threadIdx.x;
    float fe = (float)i * (1.f / 128.f);
    float ts = powf(10000.f, fe);
    float rad = (float)t / ts;
    float s, c;
    sincosf(rad, &s, &c);
    size_t base = (size_t)bt * QKVW + (size_t)n * HC;
    float x1 = qkv[base + i], x2 = qkv[base + 128 + i];
    const float sc = 0.0625f;
    size_t ob = (size_t)head * HC;
    qout[ob + i]       = (x1 * c - x2 * s) * sc;
    qout[ob + 128 + i] = (x2 * c + x1 * s) * sc;
}

// k slice of fused qkv -> dense kd (b,t,h) with RoPE
__global__ void rope_k_kernel(const float* __restrict__ qkv, float* __restrict__ kd) {
    int bt = blockIdx.x;
    int t = bt & 1023;
    int i = threadIdx.x;
    float fe = (float)i * (1.f / 128.f);
    float ts = powf(10000.f, fe);
    float rad = (float)t / ts;
    float s, c;
    sincosf(rad, &s, &c);
    size_t base = (size_t)bt * QKVW + NHD;
    float x1 = qkv[base + i], x2 = qkv[base + 128 + i];
    size_t ob = (size_t)bt * HC;
    kd[ob + i]       = x1 * c - x2 * s;
    kd[ob + 128 + i] = x2 * c + x1 * s;
}

// v slice of qkv (b,t,h) -> vT (b,h,t)  (32x32 smem tiles)
__global__ void vT_kernel(const float* __restrict__ qkv, float* __restrict__ vT) {
    __shared__ float tile[32][33];
    int b = blockIdx.z;
    int t0 = blockIdx.x * 32, h0 = blockIdx.y * 32;
    int tx = threadIdx.x, ty = threadIdx.y;       // (32, 8)
    #pragma unroll
    for (int i = 0; i < 4; i++) {
        int t = t0 + ty + i * 8;
        tile[ty + i * 8][tx] = qkv[((size_t)b * TC + t) * QKVW + NHD + HC + h0 + tx];
    }
    __syncthreads();
    #pragma unroll
    for (int i = 0; i < 4; i++) {
        int h = h0 + ty + i * 8;
        vT[((size_t)b * HC + h) * TC + t0 + tx] = tile[tx][ty + i * 8];
    }
}

// row softmax over S[32768][1024]
__global__ void softmax_kernel(float* __restrict__ S) {
    float* row = S + (size_t)blockIdx.x * TC;
    int tid = threadIdx.x;                         // 128 threads
    float4 v[2];
    v[0] = *(float4*)&row[tid * 4];
    v[1] = *(float4*)&row[512 + tid * 4];
    float m = fmaxf(fmaxf(v[0].x, v[0].y), fmaxf(v[0].z, v[0].w));
    m = fmaxf(m, fmaxf(fmaxf(v[1].x, v[1].y), fmaxf(v[1].z, v[1].w)));
    __shared__ float red[4];
    #pragma unroll
    for (int o = 16; o; o >>= 1) m = fmaxf(m, __shfl_xor_sync(0xffffffffu, m, o));
    if ((tid & 31) == 0) red[tid >> 5] = m;
    __syncthreads();
    m = fmaxf(fmaxf(red[0], red[1]), fmaxf(red[2], red[3]));
    float l = 0.f;
    #pragma unroll
    for (int q = 0; q < 2; q++) {
        float* e = &v[q].x;
        #pragma unroll
        for (int i = 0; i < 4; i++) {
            float p = __expf(fmaxf(e[i] - m, -80.f));
            e[i] = p;
            l += p;
        }
    }
    #pragma unroll
    for (int o = 16; o; o >>= 1) l += __shfl_xor_sync(0xffffffffu, l, o);
    if ((tid & 31) == 0) red[tid >> 5] = l;
    __syncthreads();
    l = red[0] + red[1] + red[2] + red[3];
    float inv = 1.f / l;
    #pragma unroll
    for (int q = 0; q < 2; q++) {
        v[q].x *= inv; v[q].y *= inv; v[q].z *= inv; v[q].w *= inv;
    }
    *(float4*)&row[tid * 4] = v[0];
    *(float4*)&row[512 + tid * 4] = v[1];
}

// ================= launch =================
extern "C" void kernel_launch(void* const* d_in, const int* in_sizes, int n_in,
                              void* d_out, int out_size) {
    const float* x0  = (const float*)d_in[0];
    const float* x1  = (const float*)d_in[1];
    const float* qw0 = (const float*)d_in[4];
    const float* kw0 = (const float*)d_in[5];
    const float* vw0 = (const float*)d_in[6];
    const float* ow0 = (const float*)d_in[7];
    const float* gw0 = (const float*)d_in[8];
    const float* uw0 = (const float*)d_in[9];
    const float* dw0 = (const float*)d_in[10];
    const float* pa0 = (const float*)d_in[11];
    const float* pf0 = (const float*)d_in[12];
    const float* qw1 = (const float*)d_in[13];
    const float* kw1 = (const float*)d_in[14];
    const float* vw1 = (const float*)d_in[15];
    const float* ow1 = (const float*)d_in[16];
    const float* gw1 = (const float*)d_in[17];
    const float* uw1 = (const float*)d_in[18];
    const float* dw1 = (const float*)d_in[19];
    const float* pa1 = (const float*)d_in[20];
    const float* pf1 = (const float*)d_in[21];

    float *pre, *qkv, *qb, *kd, *vT, *S, *enc, *resid, *hid, *gu;
    cudaGetSymbolAddress((void**)&pre,   g_pre);
    cudaGetSymbolAddress((void**)&qkv,   g_qkv);
    cudaGetSymbolAddress((void**)&qb,    g_q);
    cudaGetSymbolAddress((void**)&kd,    g_kd);
    cudaGetSymbolAddress((void**)&vT,    g_vT);
    cudaGetSymbolAddress((void**)&S,     g_S);
    cudaGetSymbolAddress((void**)&enc,   g_enc);
    cudaGetSymbolAddress((void**)&resid, g_resid);
    cudaGetSymbolAddress((void**)&hid,   g_hid);
    cudaGetSymbolAddress((void**)&gu,    g_gu);

    const int SMEM = NSTAGE * STGF * (int)sizeof(float);   // 110592
    cudaFuncSetAttribute(mma_gemm<1>, cudaFuncAttributeMaxDynamicSharedMemorySize, SMEM);
    cudaFuncSetAttribute(mma_gemm<2>, cudaFuncAttributeMaxDynamicSharedMemorySize, SMEM);
    cudaFuncSetAttribute(mma_gemm<4>, cudaFuncAttributeMaxDynamicSharedMemorySize, SMEM);
    cudaFuncSetAttribute(mma_gemm<5>, cudaFuncAttributeMaxDynamicSharedMemorySize, SMEM);
    cudaFuncSetAttribute(mma_gemm<6>, cudaFuncAttributeMaxDynamicSharedMemorySize, SMEM);
    cudaFuncSetAttribute(mma_gemm<7>, cudaFuncAttributeMaxDynamicSharedMemorySize, SMEM);
    cudaFuncSetAttribute(mma_gemm<8>, cudaFuncAttributeMaxDynamicSharedMemorySize, SMEM);

    // 1. pre = RMSNorm(x)
    rms_seg_kernel<<<BB * TC, 256>>>(x0, x1, pa0, pa1, pre);
    // 2. fused QKV projection
    mma_gemm<6><<<dim3(32, 20), 128, SMEM>>>(pre, qw0, qw1, kw0, kw1, vw0, vw1,
                                             qkv, QKVW, DC, nullptr, nullptr, nullptr);
    // 3. RoPE + v transpose
    rope_q_kernel<<<BB * TC * NQ, 128>>>(qkv, qb);
    rope_k_kernel<<<BB * TC, 128>>>(qkv, kd);
    vT_kernel<<<dim3(TC / 32, HC / 32, BB), dim3(32, 8)>>>(qkv, vT);
    // 4a. scores = q @ kd.T  (+mask)
    mma_gemm<7><<<dim3(MROWS / 128, TC / 128, BB), 128, SMEM>>>(
        qb, kd, nullptr, nullptr, nullptr, nullptr, nullptr,
        S, TC, HC, nullptr, nullptr, nullptr);
    // 4b. softmax rows
    softmax_kernel<<<BB * MROWS, 128>>>(S);
    // 4c. enc = probs @ vT.T
    mma_gemm<8><<<dim3(MROWS / 128, HC / 128, BB), 128, SMEM>>>(
        S, vT, nullptr, nullptr, nullptr, nullptr, nullptr,
        enc, HC, TC, nullptr, nullptr, nullptr);
    // 5. O-proj + residual
    mma_gemm<1><<<dim3(32, 16), 128, SMEM>>>(enc, ow0, ow1, nullptr, nullptr, nullptr, nullptr,
                                             resid, DC, NHD, x0, x1, nullptr);
    // 6. hidden = RMSNorm(resid)
    rms_cont_kernel<<<BB * TC, 256>>>(resid, pf0, pf1, hid);
    // 7. gate: gu = gelu(hid @ gw.T)
    mma_gemm<4><<<dim3(32, 128), 128, SMEM>>>(hid, gw0, gw1, nullptr, nullptr, nullptr, nullptr,
                                              gu, FC, DC, nullptr, nullptr, nullptr);
    // 8. up: gu *= hid @ uw.T
    mma_gemm<5><<<dim3(32, 128), 128, SMEM>>>(hid, uw0, uw1, nullptr, nullptr, nullptr, nullptr,
                                              gu, FC, DC, nullptr, nullptr, nullptr);
    // 9. down-proj + residual -> segmented d_out
    mma_gemm<2><<<dim3(32, 16), 128, SMEM>>>(gu, dw0, dw1, nullptr, nullptr, nullptr, nullptr,
                                             (float*)d_out, DC, FC, nullptr, nullptr, resid);
}

// round 8
// speedup vs baseline: 7.3950x; 2.0144x over previous
#include <cuda_runtime.h>
#include <cuda_fp16.h>
#include <cstdint>
#include <cstddef>

#define BB 4
#define T0C 256
#define T1C 768
#define TC 1024
#define DC 2048
#define NQ 8
#define HC 256
#define FC 16384
#define NHD 2048
#define QKVW 2560
#define MROWS 8192
#define NEGC (-2.3819763e+38f)

// ---------------- fp16 weights ----------------
__device__ __align__(16) __half g_qwh[(size_t)2*NHD*DC];
__device__ __align__(16) __half g_kwh[(size_t)2*HC*DC];
__device__ __align__(16) __half g_vwh[(size_t)2*HC*DC];
__device__ __align__(16) __half g_owh[(size_t)2*DC*NHD];
__device__ __align__(16) __half g_gwh[(size_t)2*FC*DC];
__device__ __align__(16) __half g_uwh[(size_t)2*FC*DC];
__device__ __align__(16) __half g_dwh[(size_t)2*DC*FC];

// ---------------- activations ----------------
__device__ __align__(16) __half g_preh[(size_t)BB*TC*DC];
__device__ float g_qkvf [(size_t)BB*TC*QKVW];     // fp32 QKV (pre-rope)
__device__ float g_qf   [(size_t)BB*TC*NHD];      // fp32 roped q
__device__ float g_kdf  [(size_t)BB*TC*HC];       // fp32 roped k
__device__ __align__(16) __half g_vTh [(size_t)BB*HC*TC];
__device__ float g_S    [(size_t)BB*MROWS*TC];    // fp32 scores
__device__ __align__(16) __half g_Ph  [(size_t)BB*MROWS*TC];
__device__ __align__(16) __half g_ench[(size_t)BB*TC*NHD];
__device__ float g_resid[(size_t)BB*TC*DC];
__device__ __align__(16) __half g_hidh[(size_t)BB*TC*DC];
__device__ float g_gatef[(size_t)BB*TC*FC];       // fp32 raw gate acc
__device__ __align__(16) __half g_guh [(size_t)BB*TC*FC];

__device__ __forceinline__ uint32_t smem_u32(const void* p) {
    uint32_t a;
    asm("{ .reg .u64 t; cvta.to.shared.u64 t, %1; cvt.u32.u64 %0, t; }" : "=r"(a) : "l"(p));
    return a;
}
__device__ __forceinline__ void cp16(uint32_t dst, const void* src) {
    asm volatile("cp.async.ca.shared.global [%0], [%1], 16;" :: "r"(dst), "l"(src));
}
#define CP_COMMIT() asm volatile("cp.async.commit_group;" ::: "memory")
#define CP_WAIT(n)  asm volatile("cp.async.wait_group %0;" :: "n"(n) : "memory")

__device__ __forceinline__ uint32_t f2tf32(float f) {
    uint32_t r;
    asm("cvt.rna.tf32.f32 %0, %1;" : "=r"(r) : "f"(f));
    return r;
}
__device__ __forceinline__ void mma16(float* d, const uint32_t* a, const uint32_t* b) {
    asm volatile(
        "mma.sync.aligned.m16n8k16.row.col.f32.f16.f16.f32 "
        "{%0,%1,%2,%3}, {%4,%5,%6,%7}, {%8,%9}, {%0,%1,%2,%3};"
        : "+f"(d[0]), "+f"(d[1]), "+f"(d[2]), "+f"(d[3])
        : "r"(a[0]), "r"(a[1]), "r"(a[2]), "r"(a[3]), "r"(b[0]), "r"(b[1]));
}
__device__ __forceinline__ void mma8t(float* d, const uint32_t* a, const uint32_t* b) {
    asm volatile(
        "mma.sync.aligned.m16n8k8.row.col.f32.tf32.tf32.f32 "
        "{%0,%1,%2,%3}, {%4,%5,%6,%7}, {%8,%9}, {%0,%1,%2,%3};"
        : "+f"(d[0]), "+f"(d[1]), "+f"(d[2]), "+f"(d[3])
        : "r"(a[0]), "r"(a[1]), "r"(a[2]), "r"(a[3]), "r"(b[0]), "r"(b[1]));
}

__device__ __forceinline__ float gelu_tanh(float x) {
    float x3 = x * x * x;
    return 0.5f * x * (1.f + tanhf(0.7978845608028654f * (x + 0.044715f * x3)));
}
__device__ __forceinline__ uint32_t h2u(__half2 h) { return *(uint32_t*)&h; }

// ================= fp16 cp.async multistage GEMM =================
// CTA 128x128, 4 warps 64x64, K-chunk 64, 3 stages.
// MODE 1: fp32 acc + X(seg) -> resid        MODE 2: fp32 acc + Radd -> scattered d_out
// MODE 4: fp32 raw acc (gate)               MODE 5: fp16 gelu(Radd)*acc (up, fused)
// MODE 6: fused QKV -> fp32 (y: 0-15 qw, 16-17 kw, 18-19 vw)
// MODE 8: fp16 enc (z=batch)
#define SROWH 72
#define NSTAGE 3
#define STGH (2 * 128 * SROWH)

template <int MODE>
__global__ void __launch_bounds__(128, 2)
mma_gemm(const __half* __restrict__ A,
         const __half* __restrict__ W0, const __half* __restrict__ W1,
         const __half* __restrict__ K0, const __half* __restrict__ K1,
         const __half* __restrict__ V0, const __half* __restrict__ V1,
         void* __restrict__ Cv, int Nout, int Kdim,
         const float* __restrict__ X0, const float* __restrict__ X1,
         const float* __restrict__ Radd) {
    extern __shared__ __half smh[];
    uint32_t sbase = smem_u32(smh);
    int tid = threadIdx.x, wid = tid >> 5, lane = tid & 31;
    int warp_m = wid & 1, warp_n = wid >> 1;
    int rm0 = blockIdx.x * 128;
    int rn0 = blockIdx.y * 128;
    int z = blockIdx.z;

    const __half* Wa; const __half* Wb; int wr0 = rn0;
    if (MODE == 6) {
        if (blockIdx.y < 16)      { Wa = W0; Wb = W1; wr0 = blockIdx.y * 128; }
        else if (blockIdx.y < 18) { Wa = K0; Wb = K1; wr0 = (blockIdx.y - 16) * 128; }
        else                      { Wa = V0; Wb = V1; wr0 = (blockIdx.y - 18) * 128; }
    } else { Wa = W0; Wb = W1; }

    const __half* W;
    float* Cf = (float*)Cv;
    __half* Ch = (__half*)Cv;
    if (MODE == 8) {
        A += (size_t)z * MROWS * TC;
        W = W0 + (size_t)z * HC * TC;
        Ch += (size_t)z * MROWS * HC;
    } else {
        W = ((rm0 & 1023) < T0C) ? Wa : Wb;
    }

    float acc[4][8][4];
    #pragma unroll
    for (int t = 0; t < 4; t++)
        #pragma unroll
        for (int j = 0; j < 8; j++)
            #pragma unroll
            for (int e = 0; e < 4; e++) acc[t][j][e] = 0.f;

    auto issue = [&](int c) {
        int stg = c - (c / NSTAGE) * NSTAGE;
        uint32_t sb = sbase + stg * (STGH * 2);
        int kb = c << 6;
        #pragma unroll
        for (int it = 0; it < 16; it++) {
            int idx = it * 128 + tid;
            int row = (idx >> 3) & 127;
            int sg = (idx & 7) << 3;
            if (idx < 1024)
                cp16(sb + (uint32_t)(row * SROWH + sg) * 2,
                     A + (size_t)(rm0 + row) * Kdim + kb + sg);
            else
                cp16(sb + (uint32_t)(128 * SROWH + row * SROWH + sg) * 2,
                     W + (size_t)(wr0 + row) * Kdim + kb + sg);
        }
    };

    auto compute = [&](int stg) {
        const __half* As = smh + stg * STGH;
        const __half* Ws = As + 128 * SROWH;
        int arow = warp_m * 64 + (lane >> 2);
        int brow = warp_n * 64 + (lane >> 2);
        #pragma unroll
        for (int ks = 0; ks < 4; ks++) {
            int col = ks * 16 + (lane & 3) * 2;
            uint32_t af[4][4], bf[8][2];
            #pragma unroll
            for (int t = 0; t < 4; t++) {
                const __half* p = &As[(arow + t * 16) * SROWH + col];
                af[t][0] = *(const uint32_t*)(p);
                af[t][1] = *(const uint32_t*)(p + 8 * SROWH);
                af[t][2] = *(const uint32_t*)(p + 8);
                af[t][3] = *(const uint32_t*)(p + 8 * SROWH + 8);
            }
            #pragma unroll
            for (int j = 0; j < 8; j++) {
                const __half* p = &Ws[(brow + j * 8) * SROWH + col];
                bf[j][0] = *(const uint32_t*)(p);
                bf[j][1] = *(const uint32_t*)(p + 8);
            }
            #pragma unroll
            for (int t = 0; t < 4; t++)
                #pragma unroll
                for (int j = 0; j < 8; j++)
                    mma16(acc[t][j], af[t], bf[j]);
        }
    };

    const int nch = Kdim >> 6;
    issue(0); CP_COMMIT();
    issue(1); CP_COMMIT();
    int stg = 0;
    for (int c = 0; c < nch; c++) {
        CP_WAIT(1);
        __syncthreads();
        compute(stg);
        if (++stg == NSTAGE) stg = 0;
        int nx = c + NSTAGE - 1;
        if (nx < nch) { issue(nx); CP_COMMIT(); }
        __syncthreads();
    }

    // ---------------- epilogue ----------------
    #pragma unroll
    for (int t = 0; t < 4; t++) {
        #pragma unroll
        for (int j = 0; j < 8; j++) {
            int c = rn0 + warp_n * 64 + j * 8 + (lane & 3) * 2;
            #pragma unroll
            for (int h = 0; h < 2; h++) {
                int r = rm0 + warp_m * 64 + t * 16 + (lane >> 2) + h * 8;
                float v0 = acc[t][j][h * 2 + 0];
                float v1 = acc[t][j][h * 2 + 1];
                if (MODE == 6 || MODE == 4) {
                    float2 v = {v0, v1};
                    *(float2*)&Cf[(size_t)r * Nout + c] = v;
                } else if (MODE == 8) {
                    *(__half2*)&Ch[(size_t)r * Nout + c] = __floats2half2_rn(v0, v1);
                } else if (MODE == 1) {
                    int b = r >> 10, tt = r & 1023;
                    const float* xp = (tt < T0C)
                        ? X0 + ((size_t)b * T0C + tt) * DC + c
                        : X1 + ((size_t)b * T1C + (tt - T0C)) * DC + c;
                    float2 xv = *(const float2*)xp;
                    float2 v = {v0 + xv.x, v1 + xv.y};
                    *(float2*)&Cf[(size_t)r * DC + c] = v;
                } else if (MODE == 2) {
                    float2 rv = *(const float2*)&Radd[(size_t)r * DC + c];
                    int b = r >> 10, tt = r & 1023;
                    size_t dst = (tt < T0C)
                        ? ((size_t)b * T0C + tt) * DC + c
                        : (size_t)BB * T0C * DC + ((size_t)b * T1C + (tt - T0C)) * DC + c;
                    float2 v = {v0 + rv.x, v1 + rv.y};
                    *(float2*)&Cf[dst] = v;
                } else if (MODE == 5) {
                    float2 g2 = *(const float2*)&Radd[(size_t)r * Nout + c];
                    *(__half2*)&Ch[(size_t)r * Nout + c] =
                        __floats2half2_rn(gelu_tanh(g2.x) * v0, gelu_tanh(g2.y) * v1);
                }
            }
        }
    }
}

// ================= tf32 scores GEMM (fp32 in, fp32 out + mask) =================
#define SROWF 36
#define STGF (2 * 128 * SROWF)

__global__ void __launch_bounds__(128, 2)
tf32_scores(const float* __restrict__ Q, const float* __restrict__ Kd,
            float* __restrict__ S) {
    extern __shared__ float smf[];
    uint32_t sbase = smem_u32(smf);
    int tid = threadIdx.x, wid = tid >> 5, lane = tid & 31;
    int warp_m = wid & 1, warp_n = wid >> 1;
    int rm0 = blockIdx.x * 128;
    int rn0 = blockIdx.y * 128;
    int z = blockIdx.z;
    const float* A = Q + (size_t)z * MROWS * HC;
    const float* W = Kd + (size_t)z * TC * HC;
    float* C = S + (size_t)z * MROWS * TC;

    float acc[4][8][4];
    #pragma unroll
    for (int t = 0; t < 4; t++)
        #pragma unroll
        for (int j = 0; j < 8; j++)
            #pragma unroll
            for (int e = 0; e < 4; e++) acc[t][j][e] = 0.f;

    auto issue = [&](int c) {
        int stg = c - (c / NSTAGE) * NSTAGE;
        uint32_t sb = sbase + stg * (STGF * 4);
        int kb = c << 5;
        #pragma unroll
        for (int it = 0; it < 16; it++) {
            int idx = it * 128 + tid;
            int row = (idx >> 3) & 127;
            int c4 = (idx & 7) << 2;
            if (idx < 1024)
                cp16(sb + (uint32_t)(row * SROWF + c4) * 4,
                     A + (size_t)(rm0 + row) * HC + kb + c4);
            else
                cp16(sb + (uint32_t)(128 * SROWF + row * SROWF + c4) * 4,
                     W + (size_t)(rn0 + row) * HC + kb + c4);
        }
    };
    auto compute = [&](int stg) {
        const float* As = smf + stg * STGF;
        const float* Ws = As + 128 * SROWF;
        int arow = warp_m * 64 + (lane >> 2);
        int brow = warp_n * 64 + (lane >> 2);
        #pragma unroll
        for (int ks = 0; ks < 4; ks++) {
            int ac = ks * 8 + (lane & 3);
            uint32_t af[4][4], bf[8][2];
            #pragma unroll
            for (int t = 0; t < 4; t++) {
                const float* p = &As[(arow + t * 16) * SROWF + ac];
                af[t][0] = f2tf32(p[0]);
                af[t][1] = f2tf32(p[8 * SROWF]);
                af[t][2] = f2tf32(p[4]);
                af[t][3] = f2tf32(p[8 * SROWF + 4]);
            }
            #pragma unroll
            for (int j = 0; j < 8; j++) {
                const float* p = &Ws[(brow + j * 8) * SROWF + ac];
                bf[j][0] = f2tf32(p[0]);
                bf[j][1] = f2tf32(p[4]);
            }
            #pragma unroll
            for (int t = 0; t < 4; t++)
                #pragma unroll
                for (int j = 0; j < 8; j++)
                    mma8t(acc[t][j], af[t], bf[j]);
        }
    };

    const int nch = HC >> 5;      // 8
    issue(0); CP_COMMIT();
    issue(1); CP_COMMIT();
    int stg = 0;
    for (int c = 0; c < nch; c++) {
        CP_WAIT(1);
        __syncthreads();
        compute(stg);
        if (++stg == NSTAGE) stg = 0;
        int nx = c + NSTAGE - 1;
        if (nx < nch) { issue(nx); CP_COMMIT(); }
        __syncthreads();
    }

    #pragma unroll
    for (int t = 0; t < 4; t++) {
        #pragma unroll
        for (int j = 0; j < 8; j++) {
            int c = rn0 + warp_n * 64 + j * 8 + (lane & 3) * 2;
            #pragma unroll
            for (int h = 0; h < 2; h++) {
                int r = rm0 + warp_m * 64 + t * 16 + (lane >> 2) + h * 8;
                int tt = r >> 3;
                float2 v;
                v.x = ((c < T0C) || (c <= tt)) ? acc[t][j][h * 2 + 0] : NEGC;
                v.y = ((c + 1 < T0C) || (c + 1 <= tt)) ? acc[t][j][h * 2 + 1] : NEGC;
                *(float2*)&C[(size_t)r * TC + c] = v;
            }
        }
    }
}

// ================= conversion / elementwise =================
__global__ void cvt_kernel(const float* __restrict__ src, __half* __restrict__ dst, int n4) {
    int i = blockIdx.x * blockDim.x + threadIdx.x;
    if (i >= n4) return;
    float4 v = ((const float4*)src)[i];
    __half2 h0 = __floats2half2_rn(v.x, v.y);
    __half2 h1 = __floats2half2_rn(v.z, v.w);
    uint2 u = {h2u(h0), h2u(h1)};
    ((uint2*)dst)[i] = u;
}

__device__ __forceinline__ float warp_sum(float v) {
    #pragma unroll
    for (int o = 16; o; o >>= 1) v += __shfl_down_sync(0xffffffffu, v, o);
    return v;
}

__global__ void rms_seg_kernel(const float* __restrict__ x0, const float* __restrict__ x1,
                               const float* __restrict__ s0, const float* __restrict__ s1,
                               __half* __restrict__ out) {
    int row = blockIdx.x;
    int b = row >> 10, t = row & 1023;
    const float* x; const float* s;
    if (t < T0C) { x = x0 + ((size_t)b*T0C + t)*DC; s = s0; }
    else         { x = x1 + ((size_t)b*T1C + (t - T0C))*DC; s = s1; }
    float ss = 0.f;
    for (int d = threadIdx.x; d < DC; d += 256) { float v = x[d]; ss += v*v; }
    __shared__ float red[8];
    ss = warp_sum(ss);
    if ((threadIdx.x & 31) == 0) red[threadIdx.x >> 5] = ss;
    __syncthreads();
    if (threadIdx.x < 8) {
        float v = red[threadIdx.x];
        #pragma unroll
        for (int o = 4; o; o >>= 1) v += __shfl_down_sync(0xffu, v, o);
        if (threadIdx.x == 0) red[0] = v;
    }
    __syncthreads();
    float inv = rsqrtf(red[0] * (1.f / DC) + 1e-6f);
    __half* o = out + (size_t)row * DC;
    for (int d = threadIdx.x; d < DC; d += 256)
        o[d] = __float2half(x[d] * inv * (1.f + s[d]));
}

__global__ void rms_cont_kernel(const float* __restrict__ xin,
                                const float* __restrict__ s0, const float* __restrict__ s1,
                                __half* __restrict__ out) {
    int row = blockIdx.x;
    int t = row & 1023;
    const float* x = xin + (size_t)row * DC;
    const float* s = (t < T0C) ? s0 : s1;
    float ss = 0.f;
    for (int d = threadIdx.x; d < DC; d += 256) { float v = x[d]; ss += v*v; }
    __shared__ float red[8];
    ss = warp_sum(ss);
    if ((threadIdx.x & 31) == 0) red[threadIdx.x >> 5] = ss;
    __syncthreads();
    if (threadIdx.x < 8) {
        float v = red[threadIdx.x];
        #pragma unroll
        for (int o = 4; o; o >>= 1) v += __shfl_down_sync(0xffu, v, o);
        if (threadIdx.x == 0) red[0] = v;
    }
    __syncthreads();
    float inv = rsqrtf(red[0] * (1.f / DC) + 1e-6f);
    __half* o = out + (size_t)row * DC;
    for (int d = threadIdx.x; d < DC; d += 256)
        o[d] = __float2half(x[d] * inv * (1.f + s[d]));
}

// q slice of fp32 qkv -> fp32 roped q (scaled)
__global__ void rope_q_kernel(const float* __restrict__ qkv, float* __restrict__ qout) {
    int head = blockIdx.x;
    int bt = head >> 3, n = head & 7;
    int t = bt & 1023;
    int i = threadIdx.x;
    float fe = (float)i * (1.f / 128.f);
    float ts = powf(10000.f, fe);
    float rad = (float)t / ts;
    float s, c;
    sincosf(rad, &s, &c);
    size_t base = (size_t)bt * QKVW + (size_t)n * HC;
    float x1 = qkv[base + i], x2 = qkv[base + 128 + i];
    const float sc = 0.0625f;
    size_t ob = (size_t)head * HC;
    qout[ob + i]       = (x1 * c - x2 * s) * sc;
    qout[ob + 128 + i] = (x2 * c + x1 * s) * sc;
}

__global__ void rope_k_kernel(const float* __restrict__ qkv, float* __restrict__ kd) {
    int bt = blockIdx.x;
    int t = bt & 1023;
    int i = threadIdx.x;
    float fe = (float)i * (1.f / 128.f);
    float ts = powf(10000.f, fe);
    float rad = (float)t / ts;
    float s, c;
    sincosf(rad, &s, &c);
    size_t base = (size_t)bt * QKVW + NHD;
    float x1 = qkv[base + i], x2 = qkv[base + 128 + i];
    size_t ob = (size_t)bt * HC;
    kd[ob + i]       = x1 * c - x2 * s;
    kd[ob + 128 + i] = x2 * c + x1 * s;
}

// v slice of fp32 qkv (b,t,h) -> fp16 vT (b,h,t)
__global__ void vT_kernel(const float* __restrict__ qkv, __half* __restrict__ vT) {
    __shared__ float tile[32][33];
    int b = blockIdx.z;
    int t0 = blockIdx.x * 32, h0 = blockIdx.y * 32;
    int tx = threadIdx.x, ty = threadIdx.y;
    #pragma unroll
    for (int i = 0; i < 4; i++) {
        int t = t0 + ty + i * 8;
        tile[ty + i * 8][tx] = qkv[((size_t)b * TC + t) * QKVW + NHD + HC + h0 + tx];
    }
    __syncthreads();
    #pragma unroll
    for (int i = 0; i < 4; i++) {
        int h = h0 + ty + i * 8;
        vT[((size_t)b * HC + h) * TC + t0 + tx] = __float2half(tile[tx][ty + i * 8]);
    }
}

// row softmax: fp32 S -> fp16 P
__global__ void softmax_kernel(const float* __restrict__ S, __half* __restrict__ P) {
    const float* row = S + (size_t)blockIdx.x * TC;
    __half* prow = P + (size_t)blockIdx.x * TC;
    int tid = threadIdx.x;
    float4 v[2];
    v[0] = *(const float4*)&row[tid * 4];
    v[1] = *(const float4*)&row[512 + tid * 4];
    float m = fmaxf(fmaxf(v[0].x, v[0].y), fmaxf(v[0].z, v[0].w));
    m = fmaxf(m, fmaxf(fmaxf(v[1].x, v[1].y), fmaxf(v[1].z, v[1].w)));
    __shared__ float red[4];
    #pragma unroll
    for (int o = 16; o; o >>= 1) m = fmaxf(m, __shfl_xor_sync(0xffffffffu, m, o));
    if ((tid & 31) == 0) red[tid >> 5] = m;
    __syncthreads();
    m = fmaxf(fmaxf(red[0], red[1]), fmaxf(red[2], red[3]));
    float l = 0.f;
    #pragma unroll
    for (int q = 0; q < 2; q++) {
        float* e = &v[q].x;
        #pragma unroll
        for (int i = 0; i < 4; i++) {
            float p = __expf(fmaxf(e[i] - m, -80.f));
            e[i] = p;
            l += p;
        }
    }
    #pragma unroll
    for (int o = 16; o; o >>= 1) l += __shfl_xor_sync(0xffffffffu, l, o);
    if ((tid & 31) == 0) red[tid >> 5] = l;
    __syncthreads();
    l = red[0] + red[1] + red[2] + red[3];
    float inv = 1.f / l;
    #pragma unroll
    for (int q = 0; q < 2; q++) {
        __half2 h0 = __floats2half2_rn(v[q].x * inv, v[q].y * inv);
        __half2 h1 = __floats2half2_rn(v[q].z * inv, v[q].w * inv);
        uint2 u = {h2u(h0), h2u(h1)};
        *(uint2*)&prow[q * 512 + tid * 4] = u;
    }
}

// ================= launch =================
extern "C" void kernel_launch(void* const* d_in, const int* in_sizes, int n_in,
                              void* d_out, int out_size) {
    const float* x0  = (const float*)d_in[0];
    const float* x1  = (const float*)d_in[1];
    const float* qw0 = (const float*)d_in[4];
    const float* kw0 = (const float*)d_in[5];
    const float* vw0 = (const float*)d_in[6];
    const float* ow0 = (const float*)d_in[7];
    const float* gw0 = (const float*)d_in[8];
    const float* uw0 = (const float*)d_in[9];
    const float* dw0 = (const float*)d_in[10];
    const float* pa0 = (const float*)d_in[11];
    const float* pf0 = (const float*)d_in[12];
    const float* qw1 = (const float*)d_in[13];
    const float* kw1 = (const float*)d_in[14];
    const float* vw1 = (const float*)d_in[15];
    const float* ow1 = (const float*)d_in[16];
    const float* gw1 = (const float*)d_in[17];
    const float* uw1 = (const float*)d_in[18];
    const float* dw1 = (const float*)d_in[19];
    const float* pa1 = (const float*)d_in[20];
    const float* pf1 = (const float*)d_in[21];

    __half *qwh, *kwh, *vwh, *owh, *gwh, *uwh, *dwh;
    __half *preh, *vTh, *Ph, *ench, *hidh, *guh;
    float *qkvf, *qf, *kdf, *S, *resid, *gatef;
    cudaGetSymbolAddress((void**)&qwh, g_qwh);
    cudaGetSymbolAddress((void**)&kwh, g_kwh);
    cudaGetSymbolAddress((void**)&vwh, g_vwh);
    cudaGetSymbolAddress((void**)&owh, g_owh);
    cudaGetSymbolAddress((void**)&gwh, g_gwh);
    cudaGetSymbolAddress((void**)&uwh, g_uwh);
    cudaGetSymbolAddress((void**)&dwh, g_dwh);
    cudaGetSymbolAddress((void**)&preh, g_preh);
    cudaGetSymbolAddress((void**)&qkvf, g_qkvf);
    cudaGetSymbolAddress((void**)&qf,   g_qf);
    cudaGetSymbolAddress((void**)&kdf,  g_kdf);
    cudaGetSymbolAddress((void**)&vTh,  g_vTh);
    cudaGetSymbolAddress((void**)&S,    g_S);
    cudaGetSymbolAddress((void**)&Ph,   g_Ph);
    cudaGetSymbolAddress((void**)&ench, g_ench);
    cudaGetSymbolAddress((void**)&resid, g_resid);
    cudaGetSymbolAddress((void**)&hidh, g_hidh);
    cudaGetSymbolAddress((void**)&gatef, g_gatef);
    cudaGetSymbolAddress((void**)&guh,  g_guh);

    const int SMEMH = NSTAGE * STGH * 2;   // 110592
    const int SMEMF = NSTAGE * STGF * 4;   // 110592
    cudaFuncSetAttribute(mma_gemm<1>, cudaFuncAttributeMaxDynamicSharedMemorySize, SMEMH);
    cudaFuncSetAttribute(mma_gemm<2>, cudaFuncAttributeMaxDynamicSharedMemorySize, SMEMH);
    cudaFuncSetAttribute(mma_gemm<4>, cudaFuncAttributeMaxDynamicSharedMemorySize, SMEMH);
    cudaFuncSetAttribute(mma_gemm<5>, cudaFuncAttributeMaxDynamicSharedMemorySize, SMEMH);
    cudaFuncSetAttribute(mma_gemm<6>, cudaFuncAttributeMaxDynamicSharedMemorySize, SMEMH);
    cudaFuncSetAttribute(mma_gemm<8>, cudaFuncAttributeMaxDynamicSharedMemorySize, SMEMH);
    cudaFuncSetAttribute(tf32_scores, cudaFuncAttributeMaxDynamicSharedMemorySize, SMEMF);

    // 0. weights -> fp16
    auto cvt = [&](const float* s, __half* d, size_t n) {
        int n4 = (int)(n >> 2);
        cvt_kernel<<<(n4 + 255) / 256, 256>>>(s, d, n4);
    };
    cvt(qw0, qwh,                     (size_t)NHD * DC);
    cvt(qw1, qwh + (size_t)NHD * DC,  (size_t)NHD * DC);
    cvt(kw0, kwh,                     (size_t)HC * DC);
    cvt(kw1, kwh + (size_t)HC * DC,   (size_t)HC * DC);
    cvt(vw0, vwh,                     (size_t)HC * DC);
    cvt(vw1, vwh + (size_t)HC * DC,   (size_t)HC * DC);
    cvt(ow0, owh,                     (size_t)DC * NHD);
    cvt(ow1, owh + (size_t)DC * NHD,  (size_t)DC * NHD);
    cvt(gw0, gwh,                     (size_t)FC * DC);
    cvt(gw1, gwh + (size_t)FC * DC,   (size_t)FC * DC);
    cvt(uw0, uwh,                     (size_t)FC * DC);
    cvt(uw1, uwh + (size_t)FC * DC,   (size_t)FC * DC);
    cvt(dw0, dwh,                     (size_t)DC * FC);
    cvt(dw1, dwh + (size_t)DC * FC,   (size_t)DC * FC);

    // 1. pre = RMSNorm(x) -> fp16
    rms_seg_kernel<<<BB * TC, 256>>>(x0, x1, pa0, pa1, preh);
    // 2. fused QKV -> fp32
    mma_gemm<6><<<dim3(32, 20), 128, SMEMH>>>(preh,
        qwh, qwh + (size_t)NHD * DC, kwh, kwh + (size_t)HC * DC,
        vwh, vwh + (size_t)HC * DC,
        qkvf, QKVW, DC, nullptr, nullptr, nullptr);
    // 3. RoPE (fp32 out) + V transpose (fp16 out)
    rope_q_kernel<<<BB * TC * NQ, 128>>>(qkvf, qf);
    rope_k_kernel<<<BB * TC, 128>>>(qkvf, kdf);
    vT_kernel<<<dim3(TC / 32, HC / 32, BB), dim3(32, 8)>>>(qkvf, vTh);
    // 4a. scores (tf32, fp32 in/out) + mask
    tf32_scores<<<dim3(MROWS / 128, TC / 128, BB), 128, SMEMF>>>(qf, kdf, S);
    // 4b. softmax -> fp16 probs
    softmax_kernel<<<BB * MROWS, 128>>>(S, Ph);
    // 4c. enc = P @ vT.T -> fp16
    mma_gemm<8><<<dim3(MROWS / 128, HC / 128, BB), 128, SMEMH>>>(
        Ph, vTh, nullptr, nullptr, nullptr, nullptr, nullptr,
        ench, HC, TC, nullptr, nullptr, nullptr);
    // 5. O-proj + residual -> fp32 resid
    mma_gemm<1><<<dim3(32, 16), 128, SMEMH>>>(ench,
        owh, owh + (size_t)DC * NHD, nullptr, nullptr, nullptr, nullptr,
        resid, DC, NHD, x0, x1, nullptr);
    // 6. hid = RMSNorm(resid) -> fp16
    rms_cont_kernel<<<BB * TC, 256>>>(resid, pf0, pf1, hidh);
    // 7. gate: gatef = hid @ gw.T (raw fp32)
    mma_gemm<4><<<dim3(32, 128), 128, SMEMH>>>(hidh,
        gwh, gwh + (size_t)FC * DC, nullptr, nullptr, nullptr, nullptr,
        gatef, FC, DC, nullptr, nullptr, nullptr);
    // 8. up: gu = gelu(gatef) * (hid @ uw.T) -> fp16 (single rounding)
    mma_gemm<5><<<dim3(32, 128), 128, SMEMH>>>(hidh,
        uwh, uwh + (size_t)FC * DC, nullptr, nullptr, nullptr, nullptr,
        guh, FC, DC, nullptr, nullptr, gatef);
    // 9. down-proj + residual -> segmented fp32 d_out
    mma_gemm<2><<<dim3(32, 16), 128, SMEMH>>>(guh,
        dwh, dwh + (size_t)DC * FC, nullptr, nullptr, nullptr, nullptr,
        d_out, DC, FC, nullptr, nullptr, resid);
}

// round 10
// speedup vs baseline: 7.7266x; 1.0448x over previous
#include <cuda_runtime.h>
#include <cuda_fp16.h>
#include <cstdint>
#include <cstddef>

#define BB 4
#define T0C 256
#define T1C 768
#define TC 1024
#define DC 2048
#define NQ 8
#define HC 256
#define FC 16384
#define NHD 2048
#define QKVW 2560
#define MROWS 8192
#define NEGC (-2.3819763e+38f)

// ---------------- fp16 weights ----------------
__device__ __align__(16) __half g_qwh[(size_t)2*NHD*DC];
__device__ __align__(16) __half g_kwh[(size_t)2*HC*DC];
__device__ __align__(16) __half g_vwh[(size_t)2*HC*DC];
__device__ __align__(16) __half g_owh[(size_t)2*DC*NHD];
__device__ __align__(16) __half g_gwh[(size_t)2*FC*DC];
__device__ __align__(16) __half g_uwh[(size_t)2*FC*DC];
__device__ __align__(16) __half g_dwh[(size_t)2*DC*FC];

// ---------------- activations ----------------
__device__ __align__(16) __half g_preh[(size_t)BB*TC*DC];
__device__ float g_qkvf [(size_t)BB*TC*QKVW];
__device__ __align__(16) __half g_qhh [(size_t)BB*TC*NHD];
__device__ __align__(16) __half g_kdhh[(size_t)BB*TC*HC];
__device__ __align__(16) __half g_vTh [(size_t)BB*HC*TC];
__device__ float g_S    [(size_t)BB*MROWS*TC];
__device__ __align__(16) __half g_Ph  [(size_t)BB*MROWS*TC];
__device__ __align__(16) __half g_ench[(size_t)BB*TC*NHD];
__device__ float g_resid[(size_t)BB*TC*DC];
__device__ __align__(16) __half g_hidh[(size_t)BB*TC*DC];
__device__ __align__(16) __half g_guh [(size_t)BB*TC*FC];

__device__ __forceinline__ uint32_t smem_u32(const void* p) {
    uint32_t a;
    asm("{ .reg .u64 t; cvta.to.shared.u64 t, %1; cvt.u32.u64 %0, t; }" : "=r"(a) : "l"(p));
    return a;
}
__device__ __forceinline__ void cp16(uint32_t dst, const void* src) {
    asm volatile("cp.async.ca.shared.global [%0], [%1], 16;" :: "r"(dst), "l"(src));
}
#define CP_COMMIT() asm volatile("cp.async.commit_group;" ::: "memory")
#define CP_WAIT(n)  asm volatile("cp.async.wait_group %0;" :: "n"(n) : "memory")

__device__ __forceinline__ void mma16(float* d, const uint32_t* a, const uint32_t* b) {
    asm volatile(
        "mma.sync.aligned.m16n8k16.row.col.f32.f16.f16.f32 "
        "{%0,%1,%2,%3}, {%4,%5,%6,%7}, {%8,%9}, {%0,%1,%2,%3};"
        : "+f"(d[0]), "+f"(d[1]), "+f"(d[2]), "+f"(d[3])
        : "r"(a[0]), "r"(a[1]), "r"(a[2]), "r"(a[3]), "r"(b[0]), "r"(b[1]));
}
__device__ __forceinline__ float gelu_tanh(float x) {
    float x3 = x * x * x;
    return 0.5f * x * (1.f + tanhf(0.7978845608028654f * (x + 0.044715f * x3)));
}
__device__ __forceinline__ uint32_t h2u(__half2 h) { return *(uint32_t*)&h; }

// ================= fp16 cp.async multistage GEMM =================
// CTA 128x128, 4 warps 64x64, K-chunk 64, 3 stages.
// Tail-sound pipeline: a group is committed EVERY iteration (empty when no
// issue), so CP_WAIT(1) at iteration c provably completes chunk c.
// MODE 1: fp32 acc + X(seg) -> resid    MODE 2: fp32 acc + Radd -> scattered d_out
// MODE 6: fused QKV -> fp32 (y: 0-15 qw, 16-17 kw, 18-19 vw)
// MODE 7: fp32 scores + mask (z=batch)  MODE 8: fp16 enc (z=batch)
#define SROWH 72
#define NSTAGE 3
#define STGH (2 * 128 * SROWH)

template <int MODE>
__global__ void __launch_bounds__(128, 2)
mma_gemm(const __half* __restrict__ A,
         const __half* __restrict__ W0, const __half* __restrict__ W1,
         const __half* __restrict__ K0, const __half* __restrict__ K1,
         const __half* __restrict__ V0, const __half* __restrict__ V1,
         void* __restrict__ Cv, int Nout, int Kdim,
         const float* __restrict__ X0, const float* __restrict__ X1,
         const float* __restrict__ Radd) {
    extern __shared__ __half smh[];
    uint32_t sbase = smem_u32(smh);
    int tid = threadIdx.x, wid = tid >> 5, lane = tid & 31;
    int warp_m = wid & 1, warp_n = wid >> 1;
    int rm0 = blockIdx.x * 128;
    int rn0 = blockIdx.y * 128;
    int z = blockIdx.z;

    const __half* Wa; const __half* Wb; int wr0 = rn0;
    if (MODE == 6) {
        if (blockIdx.y < 16)      { Wa = W0; Wb = W1; wr0 = blockIdx.y * 128; }
        else if (blockIdx.y < 18) { Wa = K0; Wb = K1; wr0 = (blockIdx.y - 16) * 128; }
        else                      { Wa = V0; Wb = V1; wr0 = (blockIdx.y - 18) * 128; }
    } else { Wa = W0; Wb = W1; }

    const __half* W;
    float* Cf = (float*)Cv;
    __half* Ch = (__half*)Cv;
    if (MODE == 7) {
        A += (size_t)z * MROWS * HC;
        W = W0 + (size_t)z * TC * HC;
        Cf += (size_t)z * MROWS * TC;
    } else if (MODE == 8) {
        A += (size_t)z * MROWS * TC;
        W = W0 + (size_t)z * HC * TC;
        Ch += (size_t)z * MROWS * HC;
    } else {
        W = ((rm0 & 1023) < T0C) ? Wa : Wb;
    }

    float acc[4][8][4];
    #pragma unroll
    for (int t = 0; t < 4; t++)
        #pragma unroll
        for (int j = 0; j < 8; j++)
            #pragma unroll
            for (int e = 0; e < 4; e++) acc[t][j][e] = 0.f;

    auto issue = [&](int c) {
        int stg = c - (c / NSTAGE) * NSTAGE;
        uint32_t sb = sbase + stg * (STGH * 2);
        int kb = c << 6;
        #pragma unroll
        for (int it = 0; it < 16; it++) {
            int idx = it * 128 + tid;
            int row = (idx >> 3) & 127;
            int sg = (idx & 7) << 3;
            if (idx < 1024)
                cp16(sb + (uint32_t)(row * SROWH + sg) * 2,
                     A + (size_t)(rm0 + row) * Kdim + kb + sg);
            else
                cp16(sb + (uint32_t)(128 * SROWH + row * SROWH + sg) * 2,
                     W + (size_t)(wr0 + row) * Kdim + kb + sg);
        }
    };

    auto compute = [&](int stg) {
        const __half* As = smh + stg * STGH;
        const __half* Ws = As + 128 * SROWH;
        int arow = warp_m * 64 + (lane >> 2);
        int brow = warp_n * 64 + (lane >> 2);
        #pragma unroll
        for (int ks = 0; ks < 4; ks++) {
            int col = ks * 16 + (lane & 3) * 2;
            uint32_t af[4][4], bf[8][2];
            #pragma unroll
            for (int t = 0; t < 4; t++) {
                const __half* p = &As[(arow + t * 16) * SROWH + col];
                af[t][0] = *(const uint32_t*)(p);
                af[t][1] = *(const uint32_t*)(p + 8 * SROWH);
                af[t][2] = *(const uint32_t*)(p + 8);
                af[t][3] = *(const uint32_t*)(p + 8 * SROWH + 8);
            }
            #pragma unroll
            for (int j = 0; j < 8; j++) {
                const __half* p = &Ws[(brow + j * 8) * SROWH + col];
                bf[j][0] = *(const uint32_t*)(p);
                bf[j][1] = *(const uint32_t*)(p + 8);
            }
            #pragma unroll
            for (int t = 0; t < 4; t++)
                #pragma unroll
                for (int j = 0; j < 8; j++)
                    mma16(acc[t][j], af[t], bf[j]);
        }
    };

    const int nch = Kdim >> 6;
    issue(0); CP_COMMIT();
    issue(1); CP_COMMIT();
    int stg = 0;
    for (int c = 0; c < nch; c++) {
        CP_WAIT(1);
        __syncthreads();
        compute(stg);
        if (++stg == NSTAGE) stg = 0;
        int nx = c + NSTAGE - 1;
        if (nx < nch) issue(nx);
        CP_COMMIT();                    // ALWAYS commit (empty group on tail)
        __syncthreads();
    }

    // ---------------- epilogue ----------------
    #pragma unroll
    for (int t = 0; t < 4; t++) {
        #pragma unroll
        for (int j = 0; j < 8; j++) {
            int c = rn0 + warp_n * 64 + j * 8 + (lane & 3) * 2;
            #pragma unroll
            for (int h = 0; h < 2; h++) {
                int r = rm0 + warp_m * 64 + t * 16 + (lane >> 2) + h * 8;
                float v0 = acc[t][j][h * 2 + 0];
                float v1 = acc[t][j][h * 2 + 1];
                if (MODE == 6) {
                    float2 v = {v0, v1};
                    *(float2*)&Cf[(size_t)r * Nout + c] = v;
                } else if (MODE == 8) {
                    *(__half2*)&Ch[(size_t)r * Nout + c] = __floats2half2_rn(v0, v1);
                } else if (MODE == 1) {
                    int b = r >> 10, tt = r & 1023;
                    const float* xp = (tt < T0C)
                        ? X0 + ((size_t)b * T0C + tt) * DC + c
                        : X1 + ((size_t)b * T1C + (tt - T0C)) * DC + c;
                    float2 xv = *(const float2*)xp;
                    float2 v = {v0 + xv.x, v1 + xv.y};
                    *(float2*)&Cf[(size_t)r * DC + c] = v;
                } else if (MODE == 2) {
                    float2 rv = *(const float2*)&Radd[(size_t)r * DC + c];
                    int b = r >> 10, tt = r & 1023;
                    size_t dst = (tt < T0C)
                        ? ((size_t)b * T0C + tt) * DC + c
                        : (size_t)BB * T0C * DC + ((size_t)b * T1C + (tt - T0C)) * DC + c;
                    float2 v = {v0 + rv.x, v1 + rv.y};
                    *(float2*)&Cf[dst] = v;
                } else if (MODE == 7) {
                    int tt = r >> 3;
                    float2 v;
                    v.x = ((c < T0C) || (c <= tt)) ? v0 : NEGC;
                    v.y = ((c + 1 < T0C) || (c + 1 <= tt)) ? v1 : NEGC;
                    *(float2*)&Cf[(size_t)r * TC + c] = v;
                }
            }
        }
    }
}

// ================= fused gate+up FFN kernel =================
// 256 threads, 8 warps: warps 0-3 gate (gw), warps 4-7 up (uw), same 128x128 tile.
// Epilogue: drain ALL cp.async, then gate warps write gelu(acc) to smem;
// up warps multiply -> fp16 gu.
#define STGG (384 * SROWH)          // halves per stage (A + Wg + Wu)

__global__ void __launch_bounds__(256, 1)
ffn_gateup(const __half* __restrict__ A,
           const __half* __restrict__ G0, const __half* __restrict__ G1,
           const __half* __restrict__ U0, const __half* __restrict__ U1,
           __half* __restrict__ Cg) {
    extern __shared__ __half smh[];
    uint32_t sbase = smem_u32(smh);
    int tid = threadIdx.x, wid = tid >> 5, lane = tid & 31;
    int w4 = wid & 3;
    int is_up = wid >> 2;
    int warp_m = w4 & 1, warp_n = w4 >> 1;
    int rm0 = blockIdx.x * 128;
    int rn0 = blockIdx.y * 128;
    bool seg1 = (rm0 & 1023) >= T0C;
    const __half* Wg = seg1 ? G1 : G0;
    const __half* Wu = seg1 ? U1 : U0;

    float acc[4][8][4];
    #pragma unroll
    for (int t = 0; t < 4; t++)
        #pragma unroll
        for (int j = 0; j < 8; j++)
            #pragma unroll
            for (int e = 0; e < 4; e++) acc[t][j][e] = 0.f;

    auto issue = [&](int c) {
        int stg = c - (c / NSTAGE) * NSTAGE;
        uint32_t sb = sbase + stg * (STGG * 2);
        int kb = c << 6;
        #pragma unroll
        for (int it = 0; it < 12; it++) {
            int idx = it * 256 + tid;
            int row = idx >> 3;                 // 0..383
            int sg = (idx & 7) << 3;
            const __half* src;
            if (row < 128)
                src = A + (size_t)(rm0 + row) * DC + kb + sg;
            else if (row < 256)
                src = Wg + (size_t)(rn0 + row - 128) * DC + kb + sg;
            else
                src = Wu + (size_t)(rn0 + row - 256) * DC + kb + sg;
            cp16(sb + (uint32_t)(row * SROWH + sg) * 2, src);
        }
    };

    auto compute = [&](int stg) {
        const __half* As = smh + stg * STGG;
        const __half* Ws = As + (128 + is_up * 128) * SROWH;
        int arow = warp_m * 64 + (lane >> 2);
        int brow = warp_n * 64 + (lane >> 2);
        #pragma unroll
        for (int ks = 0; ks < 4; ks++) {
            int col = ks * 16 + (lane & 3) * 2;
            uint32_t af[4][4], bf[8][2];
            #pragma unroll
            for (int t = 0; t < 4; t++) {
                const __half* p = &As[(arow + t * 16) * SROWH + col];
                af[t][0] = *(const uint32_t*)(p);
                af[t][1] = *(const uint32_t*)(p + 8 * SROWH);
                af[t][2] = *(const uint32_t*)(p + 8);
                af[t][3] = *(const uint32_t*)(p + 8 * SROWH + 8);
            }
            #pragma unroll
            for (int j = 0; j < 8; j++) {
                const __half* p = &Ws[(brow + j * 8) * SROWH + col];
                bf[j][0] = *(const uint32_t*)(p);
                bf[j][1] = *(const uint32_t*)(p + 8);
            }
            #pragma unroll
            for (int t = 0; t < 4; t++)
                #pragma unroll
                for (int j = 0; j < 8; j++)
                    mma16(acc[t][j], af[t], bf[j]);
        }
    };

    const int nch = DC >> 6;     // 32
    issue(0); CP_COMMIT();
    issue(1); CP_COMMIT();
    int stg = 0;
    for (int c = 0; c < nch; c++) {
        CP_WAIT(1);
        __syncthreads();
        compute(stg);
        if (++stg == NSTAGE) stg = 0;
        int nx = c + NSTAGE - 1;
        if (nx < nch) issue(nx);
        CP_COMMIT();                    // ALWAYS commit (empty group on tail)
        __syncthreads();
    }

    // Drain every outstanding cp.async before reusing stage smem for gelu tile.
    CP_WAIT(0);
    __syncthreads();

    float* gt = (float*)smh;            // 128 x 132 fp32 (reuses stage smem)
    if (!is_up) {
        #pragma unroll
        for (int t = 0; t < 4; t++)
            #pragma unroll
            for (int j = 0; j < 8; j++) {
                int cl = warp_n * 64 + j * 8 + (lane & 3) * 2;
                #pragma unroll
                for (int h = 0; h < 2; h++) {
                    int rl = warp_m * 64 + t * 16 + (lane >> 2) + h * 8;
                    gt[rl * 132 + cl]     = gelu_tanh(acc[t][j][h * 2 + 0]);
                    gt[rl * 132 + cl + 1] = gelu_tanh(acc[t][j][h * 2 + 1]);
                }
            }
    }
    __syncthreads();
    if (is_up) {
        #pragma unroll
        for (int t = 0; t < 4; t++)
            #pragma unroll
            for (int j = 0; j < 8; j++) {
                int cl = warp_n * 64 + j * 8 + (lane & 3) * 2;
                int c = rn0 + cl;
                #pragma unroll
                for (int h = 0; h < 2; h++) {
                    int rl = warp_m * 64 + t * 16 + (lane >> 2) + h * 8;
                    int r = rm0 + rl;
                    float g0 = gt[rl * 132 + cl];
                    float g1 = gt[rl * 132 + cl + 1];
                    *(__half2*)&Cg[(size_t)r * FC + c] =
                        __floats2half2_rn(g0 * acc[t][j][h * 2 + 0],
                                          g1 * acc[t][j][h * 2 + 1]);
                }
            }
    }
}

// ================= merged weight conversion =================
struct CvtArgs {
    const float4* s[14];
    uint2* d[14];
};
#define Q4 ((size_t)NHD * DC / 4)
#define KV4 ((size_t)HC * DC / 4)
#define G4 ((size_t)FC * DC / 4)

__global__ void cvt_all(CvtArgs a) {
    constexpr size_t sz[14] = {Q4, Q4, KV4, KV4, KV4, KV4, Q4, Q4,
                               G4, G4, G4, G4, G4, G4};
    size_t i = (size_t)blockIdx.x * 256 + threadIdx.x;
    size_t base = 0;
    #pragma unroll
    for (int r = 0; r < 14; r++) {
        if (i < base + sz[r]) {
            size_t k = i - base;
            float4 v = a.s[r][k];
            __half2 h0 = __floats2half2_rn(v.x, v.y);
            __half2 h1 = __floats2half2_rn(v.z, v.w);
            uint2 u = {h2u(h0), h2u(h1)};
            a.d[r][k] = u;
            return;
        }
        base += sz[r];
    }
}

// ================= elementwise =================
__device__ __forceinline__ float warp_sum(float v) {
    #pragma unroll
    for (int o = 16; o; o >>= 1) v += __shfl_down_sync(0xffffffffu, v, o);
    return v;
}

__global__ void rms_seg_kernel(const float* __restrict__ x0, const float* __restrict__ x1,
                               const float* __restrict__ s0, const float* __restrict__ s1,
                               __half* __restrict__ out) {
    int row = blockIdx.x;
    int b = row >> 10, t = row & 1023;
    const float* x; const float* s;
    if (t < T0C) { x = x0 + ((size_t)b*T0C + t)*DC; s = s0; }
    else         { x = x1 + ((size_t)b*T1C + (t - T0C))*DC; s = s1; }
    float ss = 0.f;
    for (int d = threadIdx.x; d < DC; d += 256) { float v = x[d]; ss += v*v; }
    __shared__ float red[8];
    ss = warp_sum(ss);
    if ((threadIdx.x & 31) == 0) red[threadIdx.x >> 5] = ss;
    __syncthreads();
    if (threadIdx.x < 8) {
        float v = red[threadIdx.x];
        #pragma unroll
        for (int o = 4; o; o >>= 1) v += __shfl_down_sync(0xffu, v, o);
        if (threadIdx.x == 0) red[0] = v;
    }
    __syncthreads();
    float inv = rsqrtf(red[0] * (1.f / DC) + 1e-6f);
    __half* o = out + (size_t)row * DC;
    for (int d = threadIdx.x; d < DC; d += 256)
        o[d] = __float2half(x[d] * inv * (1.f + s[d]));
}

__global__ void rms_cont_kernel(const float* __restrict__ xin,
                                const float* __restrict__ s0, const float* __restrict__ s1,
                                __half* __restrict__ out) {
    int row = blockIdx.x;
    int t = row & 1023;
    const float* x = xin + (size_t)row * DC;
    const float* s = (t < T0C) ? s0 : s1;
    float ss = 0.f;
    for (int d = threadIdx.x; d < DC; d += 256) { float v = x[d]; ss += v*v; }
    __shared__ float red[8];
    ss = warp_sum(ss);
    if ((threadIdx.x & 31) == 0) red[threadIdx.x >> 5] = ss;
    __syncthreads();
    if (threadIdx.x < 8) {
        float v = red[threadIdx.x];
        #pragma unroll
        for (int o = 4; o; o >>= 1) v += __shfl_down_sync(0xffu, v, o);
        if (threadIdx.x == 0) red[0] = v;
    }
    __syncthreads();
    float inv = rsqrtf(red[0] * (1.f / DC) + 1e-6f);
    __half* o = out + (size_t)row * DC;
    for (int d = threadIdx.x; d < DC; d += 256)
        o[d] = __float2half(x[d] * inv * (1.f + s[d]));
}

// q slice of fp32 qkv -> fp16 roped q (scaled); ONE rounding before scores GEMM
__global__ void rope_q_kernel(const float* __restrict__ qkv, __half* __restrict__ qout) {
    int head = blockIdx.x;
    int bt = head >> 3, n = head & 7;
    int t = bt & 1023;
    int i = threadIdx.x;
    float fe = (float)i * (1.f / 128.f);
    float ts = powf(10000.f, fe);
    float rad = (float)t / ts;
    float s, c;
    sincosf(rad, &s, &c);
    size_t base = (size_t)bt * QKVW + (size_t)n * HC;
    float x1 = qkv[base + i], x2 = qkv[base + 128 + i];
    const float sc = 0.0625f;
    size_t ob = (size_t)head * HC;
    qout[ob + i]       = __float2half((x1 * c - x2 * s) * sc);
    qout[ob + 128 + i] = __float2half((x2 * c + x1 * s) * sc);
}

__global__ void rope_k_kernel(const float* __restrict__ qkv, __half* __restrict__ kd) {
    int bt = blockIdx.x;
    int t = bt & 1023;
    int i = threadIdx.x;
    float fe = (float)i * (1.f / 128.f);
    float ts = powf(10000.f, fe);
    float rad = (float)t / ts;
    float s, c;
    sincosf(rad, &s, &c);
    size_t base = (size_t)bt * QKVW + NHD;
    float x1 = qkv[base + i], x2 = qkv[base + 128 + i];
    size_t ob = (size_t)bt * HC;
    kd[ob + i]       = __float2half(x1 * c - x2 * s);
    kd[ob + 128 + i] = __float2half(x2 * c + x1 * s);
}

// v slice of fp32 qkv (b,t,h) -> fp16 vT (b,h,t)
__global__ void vT_kernel(const float* __restrict__ qkv, __half* __restrict__ vT) {
    __shared__ float tile[32][33];
    int b = blockIdx.z;
    int t0 = blockIdx.x * 32, h0 = blockIdx.y * 32;
    int tx = threadIdx.x, ty = threadIdx.y;
    #pragma unroll
    for (int i = 0; i < 4; i++) {
        int t = t0 + ty + i * 8;
        tile[ty + i * 8][tx] = qkv[((size_t)b * TC + t) * QKVW + NHD + HC + h0 + tx];
    }
    __syncthreads();
    #pragma unroll
    for (int i = 0; i < 4; i++) {
        int h = h0 + ty + i * 8;
        vT[((size_t)b * HC + h) * TC + t0 + tx] = __float2half(tile[tx][ty + i * 8]);
    }
}

// row softmax: fp32 S -> fp16 P
__global__ void softmax_kernel(const float* __restrict__ S, __half* __restrict__ P) {
    const float* row = S + (size_t)blockIdx.x * TC;
    __half* prow = P + (size_t)blockIdx.x * TC;
    int tid = threadIdx.x;
    float4 v[2];
    v[0] = *(const float4*)&row[tid * 4];
    v[1] = *(const float4*)&row[512 + tid * 4];
    float m = fmaxf(fmaxf(v[0].x, v[0].y), fmaxf(v[0].z, v[0].w));
    m = fmaxf(m, fmaxf(fmaxf(v[1].x, v[1].y), fmaxf(v[1].z, v[1].w)));
    __shared__ float red[4];
    #pragma unroll
    for (int o = 16; o; o >>= 1) m = fmaxf(m, __shfl_xor_sync(0xffffffffu, m, o));
    if ((tid & 31) == 0) red[tid >> 5] = m;
    __syncthreads();
    m = fmaxf(fmaxf(red[0], red[1]), fmaxf(red[2], red[3]));
    float l = 0.f;
    #pragma unroll
    for (int q = 0; q < 2; q++) {
        float* e = &v[q].x;
        #pragma unroll
        for (int i = 0; i < 4; i++) {
            float p = __expf(fmaxf(e[i] - m, -80.f));
            e[i] = p;
            l += p;
        }
    }
    #pragma unroll
    for (int o = 16; o; o >>= 1) l += __shfl_xor_sync(0xffffffffu, l, o);
    if ((tid & 31) == 0) red[tid >> 5] = l;
    __syncthreads();
    l = red[0] + red[1] + red[2] + red[3];
    float inv = 1.f / l;
    #pragma unroll
    for (int q = 0; q < 2; q++) {
        __half2 h0 = __floats2half2_rn(v[q].x * inv, v[q].y * inv);
        __half2 h1 = __floats2half2_rn(v[q].z * inv, v[q].w * inv);
        uint2 u = {h2u(h0), h2u(h1)};
        *(uint2*)&prow[q * 512 + tid * 4] = u;
    }
}

// ================= launch =================
extern "C" void kernel_launch(void* const* d_in, const int* in_sizes, int n_in,
                              void* d_out, int out_size) {
    const float* x0  = (const float*)d_in[0];
    const float* x1  = (const float*)d_in[1];
    const float* qw0 = (const float*)d_in[4];
    const float* kw0 = (const float*)d_in[5];
    const float* vw0 = (const float*)d_in[6];
    const float* ow0 = (const float*)d_in[7];
    const float* gw0 = (const float*)d_in[8];
    const float* uw0 = (const float*)d_in[9];
    const float* dw0 = (const float*)d_in[10];
    const float* pa0 = (const float*)d_in[11];
    const float* pf0 = (const float*)d_in[12];
    const float* qw1 = (const float*)d_in[13];
    const float* kw1 = (const float*)d_in[14];
    const float* vw1 = (const float*)d_in[15];
    const float* ow1 = (const float*)d_in[16];
    const float* gw1 = (const float*)d_in[17];
    const float* uw1 = (const float*)d_in[18];
    const float* dw1 = (const float*)d_in[19];
    const float* pa1 = (const float*)d_in[20];
    const float* pf1 = (const float*)d_in[21];

    __half *qwh, *kwh, *vwh, *owh, *gwh, *uwh, *dwh;
    __half *preh, *qhh, *kdhh, *vTh, *Ph, *ench, *hidh, *guh;
    float *qkvf, *S, *resid;
    cudaGetSymbolAddress((void**)&qwh, g_qwh);
    cudaGetSymbolAddress((void**)&kwh, g_kwh);
    cudaGetSymbolAddress((void**)&vwh, g_vwh);
    cudaGetSymbolAddress((void**)&owh, g_owh);
    cudaGetSymbolAddress((void**)&gwh, g_gwh);
    cudaGetSymbolAddress((void**)&uwh, g_uwh);
    cudaGetSymbolAddress((void**)&dwh, g_dwh);
    cudaGetSymbolAddress((void**)&preh, g_preh);
    cudaGetSymbolAddress((void**)&qkvf, g_qkvf);
    cudaGetSymbolAddress((void**)&qhh,  g_qhh);
    cudaGetSymbolAddress((void**)&kdhh, g_kdhh);
    cudaGetSymbolAddress((void**)&vTh,  g_vTh);
    cudaGetSymbolAddress((void**)&S,    g_S);
    cudaGetSymbolAddress((void**)&Ph,   g_Ph);
    cudaGetSymbolAddress((void**)&ench, g_ench);
    cudaGetSymbolAddress((void**)&resid, g_resid);
    cudaGetSymbolAddress((void**)&hidh, g_hidh);
    cudaGetSymbolAddress((void**)&guh,  g_guh);

    const int SMEMH = NSTAGE * STGH * 2;    // 110592
    const int SMEMG = NSTAGE * STGG * 2;    // 165888
    cudaFuncSetAttribute(mma_gemm<1>, cudaFuncAttributeMaxDynamicSharedMemorySize, SMEMH);
    cudaFuncSetAttribute(mma_gemm<2>, cudaFuncAttributeMaxDynamicSharedMemorySize, SMEMH);
    cudaFuncSetAttribute(mma_gemm<6>, cudaFuncAttributeMaxDynamicSharedMemorySize, SMEMH);
    cudaFuncSetAttribute(mma_gemm<7>, cudaFuncAttributeMaxDynamicSharedMemorySize, SMEMH);
    cudaFuncSetAttribute(mma_gemm<8>, cudaFuncAttributeMaxDynamicSharedMemorySize, SMEMH);
    cudaFuncSetAttribute(ffn_gateup, cudaFuncAttributeMaxDynamicSharedMemorySize, SMEMG);

    // 0. all weights -> fp16 in one kernel
    {
        CvtArgs a;
        const float* srcs[14] = {qw0, qw1, kw0, kw1, vw0, vw1, ow0, ow1,
                                 gw0, gw1, uw0, uw1, dw0, dw1};
        __half* dsts[14] = {qwh, qwh + (size_t)NHD * DC,
                            kwh, kwh + (size_t)HC * DC,
                            vwh, vwh + (size_t)HC * DC,
                            owh, owh + (size_t)DC * NHD,
                            gwh, gwh + (size_t)FC * DC,
                            uwh, uwh + (size_t)FC * DC,
                            dwh, dwh + (size_t)DC * FC};
        for (int r = 0; r < 14; r++) {
            a.s[r] = (const float4*)srcs[r];
            a.d[r] = (uint2*)dsts[r];
        }
        size_t tot4 = 4 * Q4 + 4 * KV4 + 6 * G4;
        cvt_all<<<(unsigned)((tot4 + 255) / 256), 256>>>(a);
    }

    // 1. pre = RMSNorm(x) -> fp16
    rms_seg_kernel<<<BB * TC, 256>>>(x0, x1, pa0, pa1, preh);
    // 2. fused QKV -> fp32
    mma_gemm<6><<<dim3(32, 20), 128, SMEMH>>>(preh,
        qwh, qwh + (size_t)NHD * DC, kwh, kwh + (size_t)HC * DC,
        vwh, vwh + (size_t)HC * DC,
        qkvf, QKVW, DC, nullptr, nullptr, nullptr);
    // 3. RoPE -> fp16, V transpose -> fp16
    rope_q_kernel<<<BB * TC * NQ, 128>>>(qkvf, qhh);
    rope_k_kernel<<<BB * TC, 128>>>(qkvf, kdhh);
    vT_kernel<<<dim3(TC / 32, HC / 32, BB), dim3(32, 8)>>>(qkvf, vTh);
    // 4a. scores (fp16 MMA, fp32 out) + mask
    mma_gemm<7><<<dim3(MROWS / 128, TC / 128, BB), 128, SMEMH>>>(
        qhh, kdhh, nullptr, nullptr, nullptr, nullptr, nullptr,
        S, TC, HC, nullptr, nullptr, nullptr);
    // 4b. softmax -> fp16 probs
    softmax_kernel<<<BB * MROWS, 128>>>(S, Ph);
    // 4c. enc = P @ vT.T -> fp16
    mma_gemm<8><<<dim3(MROWS / 128, HC / 128, BB), 128, SMEMH>>>(
        Ph, vTh, nullptr, nullptr, nullptr, nullptr, nullptr,
        ench, HC, TC, nullptr, nullptr, nullptr);
    // 5. O-proj + residual -> fp32 resid
    mma_gemm<1><<<dim3(32, 16), 128, SMEMH>>>(ench,
        owh, owh + (size_t)DC * NHD, nullptr, nullptr, nullptr, nullptr,
        resid, DC, NHD, x0, x1, nullptr);
    // 6. hid = RMSNorm(resid) -> fp16
    rms_cont_kernel<<<BB * TC, 256>>>(resid, pf0, pf1, hidh);
    // 7+8. fused gate+up: gu = gelu(hid@gw.T) * (hid@uw.T) -> fp16
    ffn_gateup<<<dim3(32, 128), 256, SMEMG>>>(hidh,
        gwh, gwh + (size_t)FC * DC, uwh, uwh + (size_t)FC * DC, guh);
    // 9. down-proj + residual -> segmented fp32 d_out
    mma_gemm<2><<<dim3(32, 16), 128, SMEMH>>>(guh,
        dwh, dwh + (size_t)DC * FC, nullptr, nullptr, nullptr, nullptr,
        d_out, DC, FC, nullptr, nullptr, resid);
}